// round 2
// baseline (speedup 1.0000x reference)
#include <cuda_runtime.h>
#include <math.h>
#include <stdint.h>

// ---------------- problem constants ----------------
#define BQ     256      // batch
#define TT     100      // time steps
#define NFEAT  64
#define VV     32
#define EE     8
#define HH     512
#define NCAT   16
#define NCONT  48
#define INLEN  176      // 64 + 16*7
#define GG     2048     // 4*H
#define MT     (BQ*TT)  // 25600 rows

// ---------------- scratch (no allocations allowed) ----------------
__device__ float g_feat[MT * INLEN];     // [25600, 176]
__device__ float g_seq0[MT * HH];        // layer ping
__device__ float g_seq1[MT * HH];        // layer pong
__device__ float g_xw  [(size_t)MT * GG];// [25600, 2048]
__device__ float g_h0  [BQ * HH];
__device__ float g_h1  [BQ * HH];
__device__ float g_c   [BQ * HH];
__device__ float g_WinT[HH * INLEN];     // W_in transposed to [N,K]

// ---------------- small utility kernels ----------------
__global__ void k_transpose_win(const float* __restrict__ Win, float* __restrict__ WinT)
{
    int idx = blockIdx.x * blockDim.x + threadIdx.x;   // over 176*512
    if (idx >= INLEN * HH) return;
    int k = idx / HH, n = idx % HH;
    WinT[n * INLEN + k] = Win[idx];
}

__global__ void k_zero_state(float* a, float* b, float* c, int n)
{
    int i = blockIdx.x * blockDim.x + threadIdx.x;
    if (i < n) { a[i] = 0.f; b[i] = 0.f; c[i] = 0.f; }
}

// Build input features: cont scaled values + embedding gather.
// Column layout repeats every 11 cols per 4 source features:
//   r in [0,8): cat feature 4*blk, emb component r
//   r in [8,11): cont feature 4*blk + (r-7)
__global__ void k_build_feat(const float* __restrict__ x,
                             const float* __restrict__ mean,
                             const float* __restrict__ scale,
                             const float* __restrict__ emb,
                             float* __restrict__ feat)
{
    int idx = blockIdx.x * blockDim.x + threadIdx.x;   // over MT*INLEN
    if (idx >= MT * INLEN) return;
    int c = idx % INLEN;
    int m = idx / INLEN;
    int blk = c / 11, r = c % 11;
    float v;
    if (r < 8) {
        int k  = 4 * blk;
        int xi = (int)x[(size_t)m * NFEAT + k];        // category id (exact small int)
        v = emb[((size_t)blk * VV + xi) * EE + r];
    } else {
        int k = 4 * blk + (r - 7);
        v = (x[(size_t)m * NFEAT + k] - mean[k]) / scale[k];
    }
    feat[idx] = v;
}

// ---------------- NT SGEMM: C[M,N] = A[M,K] * W[N,K]^T (+bias)(+relu) ----------------
// 128x128 tile, BK=16, 256 threads, 8x8 microtile.
// Requires M%128==0, N%128==0, K%16==0 (all shapes here satisfy this).
__global__ __launch_bounds__(256, 2)
void k_gemm_nt(const float* __restrict__ A, const float* __restrict__ W,
               const float* __restrict__ bias, float* __restrict__ C,
               int M, int N, int K, int doRelu)
{
    __shared__ float As[16][128];
    __shared__ float Ws[16][128];

    const int tid = threadIdx.x;
    const int bm  = blockIdx.y * 128;
    const int bn  = blockIdx.x * 128;
    const int tx  = tid & 15;
    const int ty  = tid >> 4;

    float acc[8][8];
#pragma unroll
    for (int i = 0; i < 8; i++)
#pragma unroll
        for (int j = 0; j < 8; j++) acc[i][j] = 0.f;

    for (int k0 = 0; k0 < K; k0 += 16) {
#pragma unroll
        for (int i = 0; i < 2; i++) {
            int e   = tid + i * 256;      // 0..511
            int row = e >> 2;             // 0..127
            int kq  = (e & 3) << 2;       // 0,4,8,12
            float4 va = *(const float4*)(A + (size_t)(bm + row) * K + k0 + kq);
            As[kq + 0][row] = va.x; As[kq + 1][row] = va.y;
            As[kq + 2][row] = va.z; As[kq + 3][row] = va.w;
            float4 vb = *(const float4*)(W + (size_t)(bn + row) * K + k0 + kq);
            Ws[kq + 0][row] = vb.x; Ws[kq + 1][row] = vb.y;
            Ws[kq + 2][row] = vb.z; Ws[kq + 3][row] = vb.w;
        }
        __syncthreads();
#pragma unroll
        for (int kk = 0; kk < 16; kk++) {
            float a[8], b[8];
#pragma unroll
            for (int i = 0; i < 8; i++) { a[i] = As[kk][ty + 16 * i]; b[i] = Ws[kk][tx + 16 * i]; }
#pragma unroll
            for (int i = 0; i < 8; i++)
#pragma unroll
                for (int j = 0; j < 8; j++) acc[i][j] += a[i] * b[j];
        }
        __syncthreads();
    }

#pragma unroll
    for (int i = 0; i < 8; i++) {
        int r = bm + ty + 16 * i;
#pragma unroll
        for (int j = 0; j < 8; j++) {
            int cn  = bn + tx + 16 * j;
            float v = acc[i][j] + bias[cn];
            if (doRelu) v = fmaxf(v, 0.f);
            C[(size_t)r * N + cn] = v;
        }
    }
}

// ---------------- fused LSTM step ----------------
// gates[b, q*512+j] = xw[b*T+t, q*512+j] + sum_k h[b,k]*Whh[q*512+j, k] + bhh[...]
// then cell update; writes new h (double buffered), c, and relu(h) into seq_out.
// Tile: 32 batch x 32 j-cols x 4 gates per CTA. Grid (16, 8) = 128 CTAs, 128 threads.
__global__ __launch_bounds__(128)
void k_lstm_step(const float* __restrict__ xw, const float* __restrict__ Whh,
                 const float* __restrict__ bhh, float* __restrict__ seq_out,
                 int t, int parity)
{
    __shared__ float Hs[32][33];
    __shared__ float Ws[4][32][33];

    const float* hin  = parity ? g_h1 : g_h0;
    float*       hout = parity ? g_h0 : g_h1;

    const int tid = threadIdx.x;
    const int j0  = blockIdx.x * 32;
    const int b0  = blockIdx.y * 32;
    const int tx  = tid & 15;        // j: tx, tx+16
    const int ty  = tid >> 4;        // b: ty + 8*bb, bb in 0..3

    float acc[4][4][2];
#pragma unroll
    for (int q = 0; q < 4; q++)
#pragma unroll
        for (int bb = 0; bb < 4; bb++) { acc[q][bb][0] = 0.f; acc[q][bb][1] = 0.f; }

    for (int k0 = 0; k0 < HH; k0 += 32) {
#pragma unroll
        for (int i = 0; i < 2; i++) {
            int e   = tid + i * 128;
            int row = e >> 3;             // 0..31 (batch)
            int kq  = (e & 7) << 2;
            float4 v = *(const float4*)(hin + (size_t)(b0 + row) * HH + k0 + kq);
            Hs[kq + 0][row] = v.x; Hs[kq + 1][row] = v.y;
            Hs[kq + 2][row] = v.z; Hs[kq + 3][row] = v.w;
        }
#pragma unroll
        for (int i = 0; i < 8; i++) {
            int e  = tid + i * 128;
            int wr = e >> 3;              // 0..127
            int q  = wr >> 5, j = wr & 31;
            int kq = (e & 7) << 2;
            float4 v = *(const float4*)(Whh + (size_t)((q << 9) + j0 + j) * HH + k0 + kq);
            Ws[q][kq + 0][j] = v.x; Ws[q][kq + 1][j] = v.y;
            Ws[q][kq + 2][j] = v.z; Ws[q][kq + 3][j] = v.w;
        }
        __syncthreads();
#pragma unroll
        for (int kk = 0; kk < 32; kk++) {
            float h[4], w[4][2];
#pragma unroll
            for (int bb = 0; bb < 4; bb++) h[bb] = Hs[kk][ty + (bb << 3)];
#pragma unroll
            for (int q = 0; q < 4; q++) { w[q][0] = Ws[q][kk][tx]; w[q][1] = Ws[q][kk][tx + 16]; }
#pragma unroll
            for (int q = 0; q < 4; q++)
#pragma unroll
                for (int bb = 0; bb < 4; bb++) {
                    acc[q][bb][0] += h[bb] * w[q][0];
                    acc[q][bb][1] += h[bb] * w[q][1];
                }
        }
        __syncthreads();
    }

#pragma unroll
    for (int bb = 0; bb < 4; bb++) {
        int b    = b0 + ty + (bb << 3);
        size_t m = (size_t)b * TT + t;
#pragma unroll
        for (int jj = 0; jj < 2; jj++) {
            int j = j0 + tx + (jj << 4);
            float gi = acc[0][bb][jj] + xw[m * GG +           j] + bhh[          j];
            float gf = acc[1][bb][jj] + xw[m * GG +  HH     + j] + bhh[ HH     + j];
            float gg = acc[2][bb][jj] + xw[m * GG + 2 * HH  + j] + bhh[2 * HH  + j];
            float go = acc[3][bb][jj] + xw[m * GG + 3 * HH  + j] + bhh[3 * HH  + j];
            float iv = 1.f / (1.f + __expf(-gi));
            float fv = 1.f / (1.f + __expf(-gf));
            float gv = tanhf(gg);
            float ov = 1.f / (1.f + __expf(-go));
            size_t s = (size_t)b * HH + j;
            float cv = fv * g_c[s] + iv * gv;
            float hv = ov * tanhf(cv);
            g_c[s]  = cv;
            hout[s] = hv;
            seq_out[m * HH + j] = fmaxf(hv, 0.f);
        }
    }
}

// ---------------- heads ----------------
// out[0:256*48]        = last @ W_out + b_out
// out[256*48 : +256*512] = einsum('bh,nhv', last, W_cls) + b_cls  (flattened [B,16,32])
__global__ void k_head(const float* __restrict__ seq,
                       const float* __restrict__ W_out, const float* __restrict__ b_out,
                       const float* __restrict__ W_cls, const float* __restrict__ b_cls,
                       float* __restrict__ out)
{
    int idx = blockIdx.x * blockDim.x + threadIdx.x;   // B*560
    if (idx >= BQ * 560) return;
    int b = idx / 560, c = idx % 560;
    const float* last = seq + ((size_t)b * TT + (TT - 1)) * HH;
    if (c < NCONT) {
        float s = b_out[c];
#pragma unroll 4
        for (int k = 0; k < HH; k++) s += last[k] * W_out[k * NCONT + c];
        out[b * NCONT + c] = s;
    } else {
        int cc = c - NCONT;
        int n = cc >> 5, v = cc & 31;
        float s = b_cls[n * VV + v];
        const float* w = W_cls + (size_t)n * HH * VV + v;
#pragma unroll 4
        for (int k = 0; k < HH; k++) s += last[k] * w[k * VV];
        out[BQ * NCONT + (size_t)b * (NCAT * VV) + cc] = s;
    }
}

// ---------------- launch ----------------
extern "C" void kernel_launch(void* const* d_in, const int* in_sizes, int n_in,
                              void* d_out, int out_size)
{
    const float* x      = (const float*)d_in[0];
    const float* smean  = (const float*)d_in[1];
    const float* sscale = (const float*)d_in[2];
    const float* emb    = (const float*)d_in[3];
    const float* W_in   = (const float*)d_in[4];
    const float* b_in   = (const float*)d_in[5];
    const float* Wih    = (const float*)d_in[6];   // [2, 2048, 512]
    const float* Whh    = (const float*)d_in[7];   // [2, 2048, 512]
    const float* bih    = (const float*)d_in[8];   // [2, 2048]
    const float* bhh    = (const float*)d_in[9];   // [2, 2048]
    const float* W_out  = (const float*)d_in[10];
    const float* b_out  = (const float*)d_in[11];
    const float* W_cls  = (const float*)d_in[12];
    const float* b_cls  = (const float*)d_in[13];
    float* out = (float*)d_out;

    float *feat, *seq0, *seq1, *xw;
    cudaGetSymbolAddress((void**)&feat, g_feat);
    cudaGetSymbolAddress((void**)&seq0, g_seq0);
    cudaGetSymbolAddress((void**)&seq1, g_seq1);
    cudaGetSymbolAddress((void**)&xw,   g_xw);
    float *h0p, *h1p, *cp, *winT;
    cudaGetSymbolAddress((void**)&h0p,  g_h0);
    cudaGetSymbolAddress((void**)&h1p,  g_h1);
    cudaGetSymbolAddress((void**)&cp,   g_c);
    cudaGetSymbolAddress((void**)&winT, g_WinT);

    // 1) transpose W_in to [N,K]
    k_transpose_win<<<(INLEN * HH + 255) / 256, 256>>>(W_in, winT);

    // 2) build features
    k_build_feat<<<(MT * INLEN + 255) / 256, 256>>>(x, smean, sscale, emb, feat);

    // 3) input projection: seq0 = relu(feat @ W_in + b_in)   M=25600 N=512 K=176
    {
        dim3 grid(HH / 128, MT / 128);
        k_gemm_nt<<<grid, 256>>>(feat, winT, b_in, seq0, MT, HH, INLEN, 1);
    }

    // 4) two LSTM layers
    const float* seq_in  = seq0;
    float*       seq_out = seq1;
    for (int l = 0; l < 2; l++) {
        const float* Wih_l = Wih + (size_t)l * GG * HH;
        const float* Whh_l = Whh + (size_t)l * GG * HH;
        const float* bih_l = bih + (size_t)l * GG;
        const float* bhh_l = bhh + (size_t)l * GG;

        // xw = seq_in @ Wih^T + bih   M=25600 N=2048 K=512
        {
            dim3 grid(GG / 128, MT / 128);
            k_gemm_nt<<<grid, 256>>>(seq_in, Wih_l, bih_l, xw, MT, GG, HH, 0);
        }
        // zero h0,h1,c
        k_zero_state<<<(BQ * HH + 255) / 256, 256>>>(h0p, h1p, cp, BQ * HH);
        // 100 recurrent steps
        {
            dim3 grid(HH / 32, BQ / 32);
            for (int t = 0; t < TT; t++)
                k_lstm_step<<<grid, 128>>>(xw, Whh_l, bhh_l, seq_out, t, t & 1);
        }
        // swap ping/pong
        const float* tmp_in = seq_out;
        seq_out = (float*)seq_in;
        seq_in  = tmp_in;
    }

    // 5) heads (seq_in now holds layer-2 relu'd outputs)
    k_head<<<(BQ * 560 + 255) / 256, 256>>>(seq_in, W_out, b_out, W_cls, b_cls, out);
}

// round 3
// speedup vs baseline: 2.8374x; 2.8374x over previous
#include <cuda_runtime.h>
#include <math.h>
#include <stdint.h>

// ---------------- problem constants ----------------
#define BQ     256      // batch
#define TT     100      // time steps
#define NFEAT  64
#define VV     32
#define EE     8
#define HH     512
#define NCAT   16
#define NCONT  48
#define INLEN  176      // 64 + 16*7
#define GG     2048     // 4*H
#define MT     (BQ*TT)  // 25600 rows

#define NCTA_PERSIST 128
#define PERSIST_SMEM ((512*68 + 2*32*68) * 4)   // 156,672 bytes

// ---------------- scratch (no allocations allowed) ----------------
__device__ float g_feat[MT * INLEN];      // [25600, 176]
__device__ float g_seq0[MT * HH];         // layer ping
__device__ float g_seq1[MT * HH];         // layer pong
__device__ float g_xw  [(size_t)MT * GG]; // [25600, 2048]
__device__ float g_WinT[HH * INLEN];      // W_in transposed to [N,K]
__device__ float g_ht  [2 * HH * BQ];     // transposed h state, double buffered [2][512][256]
__device__ unsigned g_count;
__device__ unsigned g_gen;

// ---------------- helpers ----------------
__device__ __forceinline__ unsigned tf32u(float x) {
    unsigned u; asm("cvt.rna.tf32.f32 %0, %1;" : "=r"(u) : "f"(x)); return u;
}
__device__ __forceinline__ float tf32f(float x) { return __uint_as_float(tf32u(x)); }

__device__ __forceinline__ void mma8(float* d, const unsigned* a, const unsigned* b) {
    asm volatile("mma.sync.aligned.m16n8k8.row.col.f32.tf32.tf32.f32 "
                 "{%0,%1,%2,%3}, {%4,%5,%6,%7}, {%8,%9}, {%0,%1,%2,%3};"
                 : "+f"(d[0]), "+f"(d[1]), "+f"(d[2]), "+f"(d[3])
                 : "r"(a[0]), "r"(a[1]), "r"(a[2]), "r"(a[3]), "r"(b[0]), "r"(b[1]));
}

__device__ __forceinline__ void cpasync16(float* smem_dst, const float* gsrc) {
    unsigned s = (unsigned)__cvta_generic_to_shared(smem_dst);
    asm volatile("cp.async.cg.shared.global [%0], [%1], 16;" :: "r"(s), "l"(gsrc));
}
__device__ __forceinline__ void cpcommit() { asm volatile("cp.async.commit_group;" ::: "memory"); }
__device__ __forceinline__ void cpwait0()  { asm volatile("cp.async.wait_group 0;" ::: "memory"); }

__device__ __forceinline__ float sigm(float x)     { return 1.f / (1.f + __expf(-x)); }
__device__ __forceinline__ float tanhfast(float x) { return 2.f / (1.f + __expf(-2.f * x)) - 1.f; }

// ---------------- small utility kernels ----------------
__global__ void k_transpose_win(const float* __restrict__ Win, float* __restrict__ WinT)
{
    int idx = blockIdx.x * blockDim.x + threadIdx.x;
    if (idx >= INLEN * HH) return;
    int k = idx / HH, n = idx % HH;
    WinT[n * INLEN + k] = Win[idx];
}

__global__ void k_reset()
{
    int i = blockIdx.x * blockDim.x + threadIdx.x;
    if (i < 2 * HH * BQ) g_ht[i] = 0.f;
    if (i == 0) { g_count = 0; g_gen = 0; }
}

// Build input features: cont scaled values + embedding gather.
__global__ void k_build_feat(const float* __restrict__ x,
                             const float* __restrict__ mean,
                             const float* __restrict__ scale,
                             const float* __restrict__ emb,
                             float* __restrict__ feat)
{
    int idx = blockIdx.x * blockDim.x + threadIdx.x;
    if (idx >= MT * INLEN) return;
    int c = idx % INLEN;
    int m = idx / INLEN;
    int blk = c / 11, r = c % 11;
    float v;
    if (r < 8) {
        int k  = 4 * blk;
        int xi = (int)x[(size_t)m * NFEAT + k];
        v = emb[((size_t)blk * VV + xi) * EE + r];
    } else {
        int k = 4 * blk + (r - 7);
        v = (x[(size_t)m * NFEAT + k] - mean[k]) / scale[k];
    }
    feat[idx] = v;
}

// ---------------- tf32 NT GEMM: C[M,N] = A[M,K] * W[N,K]^T (+bias)(+relu) ----------------
// 128x128 CTA tile, BK=16, 256 threads = 8 warps (4m x 2n), warp tile 32x64.
// mma.sync m16n8k8 tf32. Requires M%128==0, N%128==0, K%16==0.
__global__ __launch_bounds__(256, 2)
void k_gemm_tf32(const float* __restrict__ A, const float* __restrict__ W,
                 const float* __restrict__ bias, float* __restrict__ C,
                 int M, int N, int K, int doRelu)
{
    __shared__ float As[16][132];
    __shared__ float Ws[16][132];

    const int tid  = threadIdx.x;
    const int bm   = blockIdx.y * 128;
    const int bn   = blockIdx.x * 128;
    const int lane = tid & 31, warp = tid >> 5;
    const int wm   = (warp & 3) * 32;   // 4 m-warps
    const int wn   = (warp >> 2) * 64;  // 2 n-warps
    const int r    = lane >> 2, cq = lane & 3;

    float acc[2][8][4];
#pragma unroll
    for (int im = 0; im < 2; im++)
#pragma unroll
        for (int in = 0; in < 8; in++)
#pragma unroll
            for (int q = 0; q < 4; q++) acc[im][in][q] = 0.f;

    for (int k0 = 0; k0 < K; k0 += 16) {
#pragma unroll
        for (int i = 0; i < 2; i++) {
            int e   = tid + i * 256;
            int row = e >> 2;
            int kq  = (e & 3) << 2;
            float4 va = *(const float4*)(A + (size_t)(bm + row) * K + k0 + kq);
            As[kq + 0][row] = tf32f(va.x); As[kq + 1][row] = tf32f(va.y);
            As[kq + 2][row] = tf32f(va.z); As[kq + 3][row] = tf32f(va.w);
            float4 vb = *(const float4*)(W + (size_t)(bn + row) * K + k0 + kq);
            Ws[kq + 0][row] = tf32f(vb.x); Ws[kq + 1][row] = tf32f(vb.y);
            Ws[kq + 2][row] = tf32f(vb.z); Ws[kq + 3][row] = tf32f(vb.w);
        }
        __syncthreads();
#pragma unroll
        for (int kk = 0; kk < 16; kk += 8) {
            unsigned a[2][4], b[8][2];
#pragma unroll
            for (int im = 0; im < 2; im++) {
                int m0 = wm + im * 16;
                a[im][0] = __float_as_uint(As[kk + cq    ][m0 + r    ]);
                a[im][1] = __float_as_uint(As[kk + cq    ][m0 + r + 8]);
                a[im][2] = __float_as_uint(As[kk + 4 + cq][m0 + r    ]);
                a[im][3] = __float_as_uint(As[kk + 4 + cq][m0 + r + 8]);
            }
#pragma unroll
            for (int in = 0; in < 8; in++) {
                int n0 = wn + in * 8;
                b[in][0] = __float_as_uint(Ws[kk + cq    ][n0 + r]);
                b[in][1] = __float_as_uint(Ws[kk + 4 + cq][n0 + r]);
            }
#pragma unroll
            for (int im = 0; im < 2; im++)
#pragma unroll
                for (int in = 0; in < 8; in++)
                    mma8(acc[im][in], a[im], b[in]);
        }
        __syncthreads();
    }

#pragma unroll
    for (int im = 0; im < 2; im++) {
        int row = bm + wm + im * 16 + r;
#pragma unroll
        for (int in = 0; in < 8; in++) {
            int col = bn + wn + in * 8 + 2 * cq;
            float2 bv = *(const float2*)(bias + col);
            float v0 = acc[im][in][0] + bv.x;
            float v1 = acc[im][in][1] + bv.y;
            float v2 = acc[im][in][2] + bv.x;
            float v3 = acc[im][in][3] + bv.y;
            if (doRelu) {
                v0 = fmaxf(v0, 0.f); v1 = fmaxf(v1, 0.f);
                v2 = fmaxf(v2, 0.f); v3 = fmaxf(v3, 0.f);
            }
            float2 o0 = make_float2(v0, v1);
            float2 o1 = make_float2(v2, v3);
            *(float2*)(C + (size_t)row * N + col)       = o0;
            *(float2*)(C + (size_t)(row + 8) * N + col) = o1;
        }
    }
}

// ---------------- persistent recurrent LSTM layer ----------------
// 128 CTAs = 4 batch-tiles(64 rows) x 32 j-tiles(16 hidden cols). Whole Whh
// slice (64 gate-rows x 512 K, gate-interleaved n = jj*4+q) resident in SMEM
// for all 100 steps. h exchanged via transposed global ping-pong (g_ht),
// streamed with cp.async.cg (L2-coherent). Cell state c lives in registers.
// Grid-wide barrier between steps via g_count/g_gen.
__device__ __forceinline__ void load_hchunk(float* dst, const float* ht_in,
                                            int k0, int m0, int tid)
{
#pragma unroll
    for (int i = 0; i < 2; i++) {
        int s  = tid + i * 256;      // 0..511
        int kk = s >> 4;             // 0..31
        int c4 = (s & 15) << 2;      // 0..60
        cpasync16(dst + kk * 68 + c4, ht_in + (size_t)(k0 + kk) * BQ + m0 + c4);
    }
}

__global__ __launch_bounds__(256, 1)
void k_lstm_persist(const float* __restrict__ xw, const float* __restrict__ Whh,
                    const float* __restrict__ bhh, float* __restrict__ seq_out)
{
    extern __shared__ float sm[];
    float* Bs = sm;                   // [512][68]  Whh slice (tf32 bits)
    float* Ha = sm + 512 * 68;        // [2][32][68] h chunk double buffer

    const int tid  = threadIdx.x, lane = tid & 31, warp = tid >> 5;
    const int j0   = blockIdx.x * 16;     // 32 j-tiles
    const int m0   = blockIdx.y * 64;     // 4 batch tiles
    const int wm   = (warp & 3) * 16;
    const int wn   = (warp >> 2) * 32;
    const int r    = lane >> 2, cq = lane & 3;

    // load Whh slice once, gate-interleaved: local col n = jj*4+q <-> Whh row q*512+j0+jj
    for (int idx = tid; idx < 64 * 128; idx += 256) {
        int n  = idx & 63;
        int k4 = idx >> 6;
        int jj = n >> 2, q = n & 3;
        float4 v = *(const float4*)(Whh + (size_t)(q * HH + j0 + jj) * HH + k4 * 4);
        Bs[(k4 * 4 + 0) * 68 + n] = tf32f(v.x);
        Bs[(k4 * 4 + 1) * 68 + n] = tf32f(v.y);
        Bs[(k4 * 4 + 2) * 68 + n] = tf32f(v.z);
        Bs[(k4 * 4 + 3) * 68 + n] = tf32f(v.w);
    }
    __syncthreads();

    float cst[4][2];                  // cell state (even lanes): [n-tile][row 0/1]
#pragma unroll
    for (int in = 0; in < 4; in++) { cst[in][0] = 0.f; cst[in][1] = 0.f; }

    for (int t = 0; t < TT; t++) {
        const int pin = t & 1;
        const float* ht_in  = g_ht + (size_t)pin * (HH * BQ);
        float*       ht_out = g_ht + (size_t)(pin ^ 1) * (HH * BQ);

        float acc[4][4];
#pragma unroll
        for (int in = 0; in < 4; in++)
#pragma unroll
            for (int q = 0; q < 4; q++) acc[in][q] = 0.f;

        load_hchunk(Ha, ht_in, 0, m0, tid);
        cpcommit();

        for (int kc = 0; kc < 16; kc++) {
            cpwait0();
            __syncthreads();
            const int buf = kc & 1;
            if (kc + 1 < 16) {
                load_hchunk(Ha + (buf ^ 1) * 32 * 68, ht_in, (kc + 1) * 32, m0, tid);
                cpcommit();
            }
            const float* hb = Ha + buf * 32 * 68;
            const int kgbase = kc * 32;
#pragma unroll
            for (int kk = 0; kk < 32; kk += 8) {
                unsigned a[4];
                a[0] = __float_as_uint(hb[(kk + cq    ) * 68 + wm + r    ]);
                a[1] = __float_as_uint(hb[(kk + cq    ) * 68 + wm + r + 8]);
                a[2] = __float_as_uint(hb[(kk + 4 + cq) * 68 + wm + r    ]);
                a[3] = __float_as_uint(hb[(kk + 4 + cq) * 68 + wm + r + 8]);
                const int kg = kgbase + kk;
#pragma unroll
                for (int in = 0; in < 4; in++) {
                    unsigned b[2];
                    b[0] = __float_as_uint(Bs[(kg + cq    ) * 68 + wn + in * 8 + r]);
                    b[1] = __float_as_uint(Bs[(kg + 4 + cq) * 68 + wn + in * 8 + r]);
                    mma8(acc[in], a, b);
                }
            }
            __syncthreads();
        }

        // epilogue: lane pair (l, l^1): even lane holds gates i,f; odd holds g,o
#pragma unroll
        for (int in = 0; in < 4; in++) {
            float xg0 = __shfl_xor_sync(0xffffffffu, acc[in][0], 1);
            float xo0 = __shfl_xor_sync(0xffffffffu, acc[in][1], 1);
            float xg1 = __shfl_xor_sync(0xffffffffu, acc[in][2], 1);
            float xo1 = __shfl_xor_sync(0xffffffffu, acc[in][3], 1);
            if (!(lane & 1)) {
                int jloc = (wn >> 2) + in * 2 + ((lane & 2) >> 1);
                int j = j0 + jloc;
#pragma unroll
                for (int rr = 0; rr < 2; rr++) {
                    int row = m0 + wm + r + rr * 8;
                    size_t xb = ((size_t)row * TT + t) * GG + j;
                    float gi = (rr ? acc[in][2] : acc[in][0]) + __ldg(xw + xb)            + __ldg(bhh + j);
                    float gf = (rr ? acc[in][3] : acc[in][1]) + __ldg(xw + xb + HH)       + __ldg(bhh + HH + j);
                    float gg = (rr ? xg1        : xg0       ) + __ldg(xw + xb + 2 * HH)   + __ldg(bhh + 2 * HH + j);
                    float go = (rr ? xo1        : xo0       ) + __ldg(xw + xb + 3 * HH)   + __ldg(bhh + 3 * HH + j);
                    float iv = sigm(gi);
                    float fv = sigm(gf);
                    float gv = tanhfast(gg);
                    float ov = sigm(go);
                    float cv = fv * cst[in][rr] + iv * gv;
                    cst[in][rr] = cv;
                    float hv = ov * tanhfast(cv);
                    ht_out[(size_t)j * BQ + row] = tf32f(hv);   // pre-rounded for next step's mma
                    seq_out[((size_t)row * TT + t) * HH + j] = fmaxf(hv, 0.f);
                }
            }
        }

        // grid barrier (release h_{t+1} to all CTAs)
        __threadfence();
        __syncthreads();
        if (tid == 0) {
            unsigned old = atomicAdd(&g_count, 1);
            if (old == NCTA_PERSIST - 1) {
                g_count = 0;
                __threadfence();
                atomicExch(&g_gen, (unsigned)(t + 1));
            } else {
                while (*(volatile unsigned*)&g_gen < (unsigned)(t + 1)) { }
                __threadfence();
            }
        }
        __syncthreads();
    }
}

// ---------------- heads ----------------
__global__ void k_head(const float* __restrict__ seq,
                       const float* __restrict__ W_out, const float* __restrict__ b_out,
                       const float* __restrict__ W_cls, const float* __restrict__ b_cls,
                       float* __restrict__ out)
{
    int idx = blockIdx.x * blockDim.x + threadIdx.x;   // B*560
    if (idx >= BQ * 560) return;
    int b = idx / 560, c = idx % 560;
    const float* last = seq + ((size_t)b * TT + (TT - 1)) * HH;
    if (c < NCONT) {
        float s = b_out[c];
#pragma unroll 4
        for (int k = 0; k < HH; k++) s += last[k] * W_out[k * NCONT + c];
        out[b * NCONT + c] = s;
    } else {
        int cc = c - NCONT;
        int n = cc >> 5, v = cc & 31;
        float s = b_cls[n * VV + v];
        const float* w = W_cls + (size_t)n * HH * VV + v;
#pragma unroll 4
        for (int k = 0; k < HH; k++) s += last[k] * w[k * VV];
        out[BQ * NCONT + (size_t)b * (NCAT * VV) + cc] = s;
    }
}

// ---------------- launch ----------------
extern "C" void kernel_launch(void* const* d_in, const int* in_sizes, int n_in,
                              void* d_out, int out_size)
{
    const float* x      = (const float*)d_in[0];
    const float* smean  = (const float*)d_in[1];
    const float* sscale = (const float*)d_in[2];
    const float* emb    = (const float*)d_in[3];
    const float* W_in   = (const float*)d_in[4];
    const float* b_in   = (const float*)d_in[5];
    const float* Wih    = (const float*)d_in[6];   // [2, 2048, 512]
    const float* Whh    = (const float*)d_in[7];   // [2, 2048, 512]
    const float* bih    = (const float*)d_in[8];   // [2, 2048]
    const float* bhh    = (const float*)d_in[9];   // [2, 2048]
    const float* W_out  = (const float*)d_in[10];
    const float* b_out  = (const float*)d_in[11];
    const float* W_cls  = (const float*)d_in[12];
    const float* b_cls  = (const float*)d_in[13];
    float* out = (float*)d_out;

    float *feat, *seq0, *seq1, *xw, *winT;
    cudaGetSymbolAddress((void**)&feat, g_feat);
    cudaGetSymbolAddress((void**)&seq0, g_seq0);
    cudaGetSymbolAddress((void**)&seq1, g_seq1);
    cudaGetSymbolAddress((void**)&xw,   g_xw);
    cudaGetSymbolAddress((void**)&winT, g_WinT);

    cudaFuncSetAttribute(k_lstm_persist, cudaFuncAttributeMaxDynamicSharedMemorySize,
                         PERSIST_SMEM);

    // 1) transpose W_in to [N,K]
    k_transpose_win<<<(INLEN * HH + 255) / 256, 256>>>(W_in, winT);

    // 2) build features
    k_build_feat<<<(MT * INLEN + 255) / 256, 256>>>(x, smean, sscale, emb, feat);

    // 3) input projection: seq0 = relu(feat @ W_in + b_in)   M=25600 N=512 K=176
    {
        dim3 grid(HH / 128, MT / 128);
        k_gemm_tf32<<<grid, 256>>>(feat, winT, b_in, seq0, MT, HH, INLEN, 1);
    }

    // 4) two LSTM layers
    const float* seq_in  = seq0;
    float*       seq_out = seq1;
    for (int l = 0; l < 2; l++) {
        const float* Wih_l = Wih + (size_t)l * GG * HH;
        const float* Whh_l = Whh + (size_t)l * GG * HH;
        const float* bih_l = bih + (size_t)l * GG;
        const float* bhh_l = bhh + (size_t)l * GG;

        // xw = seq_in @ Wih^T + bih   M=25600 N=2048 K=512
        {
            dim3 grid(GG / 128, MT / 128);
            k_gemm_tf32<<<grid, 256>>>(seq_in, Wih_l, bih_l, xw, MT, GG, HH, 0);
        }
        // reset h state + barrier vars
        k_reset<<<(2 * HH * BQ + 255) / 256, 256>>>();
        // persistent 100-step recurrence
        {
            dim3 grid(HH / 16, BQ / 64);   // (32, 4) = 128 CTAs
            k_lstm_persist<<<grid, 256, PERSIST_SMEM>>>(xw, Whh_l, bhh_l, seq_out);
        }
        // swap ping/pong
        const float* tmp_in = seq_out;
        seq_out = (float*)seq_in;
        seq_in  = tmp_in;
    }

    // 5) heads
    k_head<<<(BQ * 560 + 255) / 256, 256>>>(seq_in, W_out, b_out, W_cls, b_cls, out);
}

// round 4
// speedup vs baseline: 4.0280x; 1.4196x over previous
#include <cuda_runtime.h>
#include <math.h>
#include <stdint.h>

// ---------------- problem constants ----------------
#define BQ     256      // batch
#define TT     100      // time steps
#define NFEAT  64
#define VV     32
#define EE     8
#define HH     512
#define NCAT   16
#define NCONT  48
#define INLEN  176      // 64 + 16*7
#define GG     2048     // 4*H
#define MT     (BQ*TT)  // 25600 rows

#define NCTA_PERSIST 128
// persist smem: Bs 512*72 + Ha 3*64*72 + Xs 64*68 floats
#define P_BS_F   (512*72)
#define P_HA_F   (3*64*72)
#define P_XS_F   (64*68)
#define PERSIST_SMEM ((P_BS_F + P_HA_F + P_XS_F) * 4)   // 220,160 B

// GEMM smem: 4 stages x (A 128x20 + W 128x20) floats
#define GSTAGE_F (128*20)
#define GEMM_SMEM (4 * 2 * GSTAGE_F * 4)                 // 81,920 B

// ---------------- scratch (no allocations allowed) ----------------
__device__ float g_feat[MT * INLEN];      // [25600, 176] (tf32-rounded)
__device__ float g_seq0[MT * HH];         // layer ping (tf32-rounded activations)
__device__ float g_seq1[MT * HH];         // layer pong
__device__ float g_xw  [(size_t)MT * GG]; // [25600, 2048] f32 gates
__device__ float g_WinT[HH * INLEN];      // W_in^T, tf32-rounded
__device__ float g_WihR[2 * GG * HH];     // Wih, tf32-rounded
__device__ float g_ht  [2 * HH * BQ];     // transposed h state, double buffered
__device__ unsigned g_count;
__device__ unsigned g_gen;

// ---------------- helpers ----------------
__device__ __forceinline__ unsigned tf32u(float x) {
    unsigned u; asm("cvt.rna.tf32.f32 %0, %1;" : "=r"(u) : "f"(x)); return u;
}
__device__ __forceinline__ float tf32f(float x) { return __uint_as_float(tf32u(x)); }

__device__ __forceinline__ void mma8(float* d, const unsigned* a, const unsigned* b) {
    asm volatile("mma.sync.aligned.m16n8k8.row.col.f32.tf32.tf32.f32 "
                 "{%0,%1,%2,%3}, {%4,%5,%6,%7}, {%8,%9}, {%0,%1,%2,%3};"
                 : "+f"(d[0]), "+f"(d[1]), "+f"(d[2]), "+f"(d[3])
                 : "r"(a[0]), "r"(a[1]), "r"(a[2]), "r"(a[3]), "r"(b[0]), "r"(b[1]));
}

__device__ __forceinline__ void cpasync16(float* smem_dst, const float* gsrc) {
    unsigned s = (unsigned)__cvta_generic_to_shared(smem_dst);
    asm volatile("cp.async.cg.shared.global [%0], [%1], 16;" :: "r"(s), "l"(gsrc));
}
__device__ __forceinline__ void cpcommit() { asm volatile("cp.async.commit_group;" ::: "memory"); }
template<int N> __device__ __forceinline__ void cpwaitN() {
    asm volatile("cp.async.wait_group %0;" :: "n"(N) : "memory");
}

__device__ __forceinline__ float sigm(float x)     { return 1.f / (1.f + __expf(-x)); }
__device__ __forceinline__ float tanhfast(float x) { return 2.f / (1.f + __expf(-2.f * x)) - 1.f; }

// ---------------- small utility kernels ----------------
__global__ void k_transpose_win(const float* __restrict__ Win, float* __restrict__ WinT)
{
    int idx = blockIdx.x * blockDim.x + threadIdx.x;
    if (idx >= INLEN * HH) return;
    int k = idx / HH, n = idx % HH;
    WinT[n * INLEN + k] = tf32f(Win[idx]);
}

__global__ void k_round_wih(const float* __restrict__ W, float* __restrict__ R)
{
    int i = blockIdx.x * blockDim.x + threadIdx.x;
    if (i < 2 * GG * HH) R[i] = tf32f(W[i]);
}

__global__ void k_reset()
{
    int i = blockIdx.x * blockDim.x + threadIdx.x;
    if (i < 2 * HH * BQ) g_ht[i] = 0.f;
    if (i == 0) { g_count = 0; g_gen = 0; }
}

// Build input features: cont scaled values + embedding gather (tf32-rounded).
__global__ void k_build_feat(const float* __restrict__ x,
                             const float* __restrict__ mean,
                             const float* __restrict__ scale,
                             const float* __restrict__ emb,
                             float* __restrict__ feat)
{
    int idx = blockIdx.x * blockDim.x + threadIdx.x;
    if (idx >= MT * INLEN) return;
    int c = idx % INLEN;
    int m = idx / INLEN;
    int blk = c / 11, r = c % 11;
    float v;
    if (r < 8) {
        int k  = 4 * blk;
        int xi = (int)x[(size_t)m * NFEAT + k];
        v = emb[((size_t)blk * VV + xi) * EE + r];
    } else {
        int k = 4 * blk + (r - 7);
        v = (x[(size_t)m * NFEAT + k] - mean[k]) / scale[k];
    }
    feat[idx] = tf32f(v);
}

// ---------------- tf32 NT GEMM, 4-stage cp.async pipeline ----------------
// C[M,N] = A[M,K] * W[N,K]^T (+bias)(+relu)(+tf32 round)
// 128x128 CTA tile, BK=16, 256 threads = 8 warps (4m x 2n), warp tile 32x64.
// A/W assumed pre-rounded to tf32. smem layout [row][k] stride 20 (conflict-free).
__device__ __forceinline__ void gemm_load_stage(float* dstA, float* dstW,
                                                const float* A, const float* W,
                                                int bm, int bn, int K, int kc, int tid)
{
    int k0 = kc << 4;
#pragma unroll
    for (int i = 0; i < 2; i++) {
        int e   = tid + i * 256;   // 0..511
        int row = e >> 2;
        int q   = (e & 3) << 2;
        cpasync16(dstA + row * 20 + q, A + (size_t)(bm + row) * K + k0 + q);
        cpasync16(dstW + row * 20 + q, W + (size_t)(bn + row) * K + k0 + q);
    }
}

__global__ __launch_bounds__(256, 2)
void k_gemm_tf32(const float* __restrict__ A, const float* __restrict__ W,
                 const float* __restrict__ bias, float* __restrict__ C,
                 int M, int N, int K, int flags)   // bit0: relu, bit1: round output
{
    extern __shared__ float sm[];
    float* As = sm;                       // [4][128*20]
    float* Ws = sm + 4 * GSTAGE_F;

    const int tid  = threadIdx.x;
    const int bm   = blockIdx.y * 128;
    const int bn   = blockIdx.x * 128;
    const int lane = tid & 31, warp = tid >> 5;
    const int wm   = (warp & 3) * 32;
    const int wn   = (warp >> 2) * 64;
    const int r    = lane >> 2, cq = lane & 3;
    const int NK   = K >> 4;

    float acc[2][8][4];
#pragma unroll
    for (int im = 0; im < 2; im++)
#pragma unroll
        for (int in = 0; in < 8; in++)
#pragma unroll
            for (int q = 0; q < 4; q++) acc[im][in][q] = 0.f;

    gemm_load_stage(As, Ws, A, W, bm, bn, K, 0, tid); cpcommit();
    gemm_load_stage(As + GSTAGE_F, Ws + GSTAGE_F, A, W, bm, bn, K, 1, tid); cpcommit();
    gemm_load_stage(As + 2 * GSTAGE_F, Ws + 2 * GSTAGE_F, A, W, bm, bn, K, 2, tid); cpcommit();

    for (int kc = 0; kc < NK; kc++) {
        if      (kc < NK - 2) cpwaitN<2>();
        else if (kc < NK - 1) cpwaitN<1>();
        else                  cpwaitN<0>();
        __syncthreads();
        if (kc + 3 < NK) {
            int s = (kc + 3) & 3;
            gemm_load_stage(As + s * GSTAGE_F, Ws + s * GSTAGE_F, A, W, bm, bn, K, kc + 3, tid);
            cpcommit();
        }
        const float* as = As + (kc & 3) * GSTAGE_F;
        const float* ws = Ws + (kc & 3) * GSTAGE_F;
#pragma unroll
        for (int kk = 0; kk < 16; kk += 8) {
            unsigned a[2][4], b[8][2];
#pragma unroll
            for (int im = 0; im < 2; im++) {
                int m0 = wm + im * 16;
                a[im][0] = __float_as_uint(as[(m0 + r    ) * 20 + kk + cq    ]);
                a[im][1] = __float_as_uint(as[(m0 + r + 8) * 20 + kk + cq    ]);
                a[im][2] = __float_as_uint(as[(m0 + r    ) * 20 + kk + 4 + cq]);
                a[im][3] = __float_as_uint(as[(m0 + r + 8) * 20 + kk + 4 + cq]);
            }
#pragma unroll
            for (int in = 0; in < 8; in++) {
                int n0 = wn + in * 8;
                b[in][0] = __float_as_uint(ws[(n0 + r) * 20 + kk + cq    ]);
                b[in][1] = __float_as_uint(ws[(n0 + r) * 20 + kk + 4 + cq]);
            }
#pragma unroll
            for (int im = 0; im < 2; im++)
#pragma unroll
                for (int in = 0; in < 8; in++)
                    mma8(acc[im][in], a[im], b[in]);
        }
    }

    const int doRelu  = flags & 1;
    const int doRound = flags & 2;
#pragma unroll
    for (int im = 0; im < 2; im++) {
        int row = bm + wm + im * 16 + r;
#pragma unroll
        for (int in = 0; in < 8; in++) {
            int col = bn + wn + in * 8 + 2 * cq;
            float2 bv = *(const float2*)(bias + col);
            float v0 = acc[im][in][0] + bv.x;
            float v1 = acc[im][in][1] + bv.y;
            float v2 = acc[im][in][2] + bv.x;
            float v3 = acc[im][in][3] + bv.y;
            if (doRelu) {
                v0 = fmaxf(v0, 0.f); v1 = fmaxf(v1, 0.f);
                v2 = fmaxf(v2, 0.f); v3 = fmaxf(v3, 0.f);
            }
            if (doRound) {
                v0 = tf32f(v0); v1 = tf32f(v1); v2 = tf32f(v2); v3 = tf32f(v3);
            }
            *(float2*)(C + (size_t)row * N + col)       = make_float2(v0, v1);
            *(float2*)(C + (size_t)(row + 8) * N + col) = make_float2(v2, v3);
        }
    }
}

// ---------------- persistent recurrent LSTM layer ----------------
// 128 CTAs = 4 batch-tiles(64) x 32 j-tiles(16). Whh slice resident in SMEM.
// Per step: xw gate tile (64x64) + h chunks streamed via one cp.async pipeline.
#define KCH 64
#define NCH (HH / KCH)   // 8

__global__ __launch_bounds__(256, 1)
void k_lstm_persist(const float* __restrict__ xw, const float* __restrict__ Whh,
                    const float* __restrict__ bhh, float* __restrict__ seq_out)
{
    extern __shared__ float sm[];
    float* Bs = sm;                       // [512][72]  Whh slice (tf32)
    float* Ha = sm + P_BS_F;              // [3][64][72] h chunk triple buffer
    float* Xs = sm + P_BS_F + P_HA_F;     // [64][68]   xw gate tile

    const int tid  = threadIdx.x, lane = tid & 31, warp = tid >> 5;
    const int j0   = blockIdx.x * 16;     // 32 j-tiles
    const int m0   = blockIdx.y * 64;     // 4 batch tiles
    const int wm   = (warp & 3) * 16;
    const int wn   = (warp >> 2) * 32;
    const int r    = lane >> 2, cq = lane & 3;

    // one-time Whh slice load, gate-interleaved: col n = jj*4+q <-> row q*512+j0+jj
    for (int idx = tid; idx < 64 * 128; idx += 256) {
        int n  = idx & 63;
        int k4 = idx >> 6;
        int jj = n >> 2, q = n & 3;
        float4 v = *(const float4*)(Whh + (size_t)(q * HH + j0 + jj) * HH + k4 * 4);
        Bs[(k4 * 4 + 0) * 72 + n] = tf32f(v.x);
        Bs[(k4 * 4 + 1) * 72 + n] = tf32f(v.y);
        Bs[(k4 * 4 + 2) * 72 + n] = tf32f(v.z);
        Bs[(k4 * 4 + 3) * 72 + n] = tf32f(v.w);
    }

    // hoist bhh (per-lane j values; valid for all lanes, used by even lanes)
    const int jbase = (wn >> 2) + ((lane & 2) >> 1);
    float bh[4][4];
#pragma unroll
    for (int in = 0; in < 4; in++) {
        int j = j0 + jbase + in * 2;
#pragma unroll
        for (int q = 0; q < 4; q++) bh[in][q] = bhh[q * HH + j];
    }
    __syncthreads();

    float cst[4][2];
#pragma unroll
    for (int in = 0; in < 4; in++) { cst[in][0] = 0.f; cst[in][1] = 0.f; }

    for (int t = 0; t < TT; t++) {
        const int pin = t & 1;
        const float* ht_in  = g_ht + (size_t)pin * (HH * BQ);
        float*       ht_out = g_ht + (size_t)(pin ^ 1) * (HH * BQ);

        float acc[4][4];
#pragma unroll
        for (int in = 0; in < 4; in++)
#pragma unroll
            for (int q = 0; q < 4; q++) acc[in][q] = 0.f;

        // group 0: xw tile + h chunk 0 ; group 1: h chunk 1
        {
#pragma unroll
            for (int i = 0; i < 4; i++) {
                int s   = tid + i * 256;        // 0..1023
                int row = s >> 4;
                int q   = (s >> 2) & 3;
                int f4  = (s & 3) << 2;
                cpasync16(Xs + row * 68 + q * 16 + f4,
                          xw + ((size_t)(m0 + row) * TT + t) * GG + q * HH + j0 + f4);
            }
#pragma unroll
            for (int i = 0; i < 4; i++) {
                int s  = tid + i * 256;
                int kk = s >> 4;                // 0..63
                int c4 = (s & 15) << 2;
                cpasync16(Ha + kk * 72 + c4, ht_in + (size_t)kk * BQ + m0 + c4);
            }
            cpcommit();
#pragma unroll
            for (int i = 0; i < 4; i++) {
                int s  = tid + i * 256;
                int kk = s >> 4;
                int c4 = (s & 15) << 2;
                cpasync16(Ha + 64 * 72 + kk * 72 + c4,
                          ht_in + (size_t)(KCH + kk) * BQ + m0 + c4);
            }
            cpcommit();
        }

        for (int kc = 0; kc < NCH; kc++) {
            if (kc < NCH - 1) cpwaitN<1>(); else cpwaitN<0>();
            __syncthreads();
            if (kc + 2 < NCH) {
                float* dst = Ha + ((kc + 2) % 3) * (64 * 72);
                const int k0 = (kc + 2) * KCH;
#pragma unroll
                for (int i = 0; i < 4; i++) {
                    int s  = tid + i * 256;
                    int kk = s >> 4;
                    int c4 = (s & 15) << 2;
                    cpasync16(dst + kk * 72 + c4, ht_in + (size_t)(k0 + kk) * BQ + m0 + c4);
                }
                cpcommit();
            }
            const float* hb = Ha + (kc % 3) * (64 * 72);
            const int kgbase = kc * KCH;
#pragma unroll
            for (int kk = 0; kk < KCH; kk += 8) {
                unsigned a[4];
                a[0] = __float_as_uint(hb[(kk + cq    ) * 72 + wm + r    ]);
                a[1] = __float_as_uint(hb[(kk + cq    ) * 72 + wm + r + 8]);
                a[2] = __float_as_uint(hb[(kk + 4 + cq) * 72 + wm + r    ]);
                a[3] = __float_as_uint(hb[(kk + 4 + cq) * 72 + wm + r + 8]);
                const int kg = kgbase + kk;
#pragma unroll
                for (int in = 0; in < 4; in++) {
                    unsigned b[2];
                    b[0] = __float_as_uint(Bs[(kg + cq    ) * 72 + wn + in * 8 + r]);
                    b[1] = __float_as_uint(Bs[(kg + 4 + cq) * 72 + wn + in * 8 + r]);
                    mma8(acc[in], a, b);
                }
            }
        }
        __syncthreads();   // all mma reads of Xs/Ha done; Xs consumed below

        // epilogue: lane pair (l, l^1): even lane holds gates i,f; odd holds g,o
#pragma unroll
        for (int in = 0; in < 4; in++) {
            float xg0 = __shfl_xor_sync(0xffffffffu, acc[in][0], 1);
            float xo0 = __shfl_xor_sync(0xffffffffu, acc[in][1], 1);
            float xg1 = __shfl_xor_sync(0xffffffffu, acc[in][2], 1);
            float xo1 = __shfl_xor_sync(0xffffffffu, acc[in][3], 1);
            if (!(lane & 1)) {
                int jloc = jbase + in * 2;
                int j = j0 + jloc;
#pragma unroll
                for (int rr = 0; rr < 2; rr++) {
                    int rowl = wm + r + rr * 8;
                    int row  = m0 + rowl;
                    const float* xr = Xs + rowl * 68 + jloc;
                    float gi = (rr ? acc[in][2] : acc[in][0]) + xr[0 ]      + bh[in][0];
                    float gf = (rr ? acc[in][3] : acc[in][1]) + xr[16]      + bh[in][1];
                    float gg = (rr ? xg1        : xg0       ) + xr[32]      + bh[in][2];
                    float go = (rr ? xo1        : xo0       ) + xr[48]      + bh[in][3];
                    float iv = sigm(gi);
                    float fv = sigm(gf);
                    float gv = tanhfast(gg);
                    float ov = sigm(go);
                    float cv = fv * cst[in][rr] + iv * gv;
                    cst[in][rr] = cv;
                    float hv = ov * tanhfast(cv);
                    ht_out[(size_t)j * BQ + row] = tf32f(hv);
                    seq_out[((size_t)row * TT + t) * HH + j] = tf32f(fmaxf(hv, 0.f));
                }
            }
        }

        // grid barrier (release h_{t+1} to all CTAs)
        __threadfence();
        __syncthreads();
        if (tid == 0) {
            unsigned old = atomicAdd(&g_count, 1);
            if (old == NCTA_PERSIST - 1) {
                g_count = 0;
                __threadfence();
                atomicExch(&g_gen, (unsigned)(t + 1));
            } else {
                while (*(volatile unsigned*)&g_gen < (unsigned)(t + 1)) { }
                __threadfence();
            }
        }
        __syncthreads();
    }
}

// ---------------- heads ----------------
__global__ void k_head(const float* __restrict__ seq,
                       const float* __restrict__ W_out, const float* __restrict__ b_out,
                       const float* __restrict__ W_cls, const float* __restrict__ b_cls,
                       float* __restrict__ out)
{
    int idx = blockIdx.x * blockDim.x + threadIdx.x;   // B*560
    if (idx >= BQ * 560) return;
    int b = idx / 560, c = idx % 560;
    const float* last = seq + ((size_t)b * TT + (TT - 1)) * HH;
    if (c < NCONT) {
        float s = b_out[c];
#pragma unroll 4
        for (int k = 0; k < HH; k++) s += last[k] * W_out[k * NCONT + c];
        out[b * NCONT + c] = s;
    } else {
        int cc = c - NCONT;
        int n = cc >> 5, v = cc & 31;
        float s = b_cls[n * VV + v];
        const float* w = W_cls + (size_t)n * HH * VV + v;
#pragma unroll 4
        for (int k = 0; k < HH; k++) s += last[k] * w[k * VV];
        out[BQ * NCONT + (size_t)b * (NCAT * VV) + cc] = s;
    }
}

// ---------------- launch ----------------
extern "C" void kernel_launch(void* const* d_in, const int* in_sizes, int n_in,
                              void* d_out, int out_size)
{
    const float* x      = (const float*)d_in[0];
    const float* smean  = (const float*)d_in[1];
    const float* sscale = (const float*)d_in[2];
    const float* emb    = (const float*)d_in[3];
    const float* W_in   = (const float*)d_in[4];
    const float* b_in   = (const float*)d_in[5];
    const float* Wih    = (const float*)d_in[6];   // [2, 2048, 512]
    const float* Whh    = (const float*)d_in[7];   // [2, 2048, 512]
    const float* bih    = (const float*)d_in[8];   // [2, 2048]
    const float* bhh    = (const float*)d_in[9];   // [2, 2048]
    const float* W_out  = (const float*)d_in[10];
    const float* b_out  = (const float*)d_in[11];
    const float* W_cls  = (const float*)d_in[12];
    const float* b_cls  = (const float*)d_in[13];
    float* out = (float*)d_out;

    float *feat, *seq0, *seq1, *xw, *winT, *wihR;
    cudaGetSymbolAddress((void**)&feat, g_feat);
    cudaGetSymbolAddress((void**)&seq0, g_seq0);
    cudaGetSymbolAddress((void**)&seq1, g_seq1);
    cudaGetSymbolAddress((void**)&xw,   g_xw);
    cudaGetSymbolAddress((void**)&winT, g_WinT);
    cudaGetSymbolAddress((void**)&wihR, g_WihR);

    cudaFuncSetAttribute(k_lstm_persist, cudaFuncAttributeMaxDynamicSharedMemorySize,
                         PERSIST_SMEM);
    cudaFuncSetAttribute(k_gemm_tf32, cudaFuncAttributeMaxDynamicSharedMemorySize,
                         GEMM_SMEM);

    // 1) weight prep (tf32 rounding)
    k_transpose_win<<<(INLEN * HH + 255) / 256, 256>>>(W_in, winT);
    k_round_wih<<<(2 * GG * HH + 255) / 256, 256>>>(Wih, wihR);

    // 2) build features
    k_build_feat<<<(MT * INLEN + 255) / 256, 256>>>(x, smean, sscale, emb, feat);

    // 3) input projection: seq0 = round(relu(feat @ W_in + b_in))
    {
        dim3 grid(HH / 128, MT / 128);
        k_gemm_tf32<<<grid, 256, GEMM_SMEM>>>(feat, winT, b_in, seq0, MT, HH, INLEN, 3);
    }

    // 4) two LSTM layers
    const float* seq_in  = seq0;
    float*       seq_out = seq1;
    for (int l = 0; l < 2; l++) {
        const float* Wih_l = wihR + (size_t)l * GG * HH;
        const float* Whh_l = Whh  + (size_t)l * GG * HH;
        const float* bih_l = bih  + (size_t)l * GG;
        const float* bhh_l = bhh  + (size_t)l * GG;

        // xw = seq_in @ Wih^T + bih   (f32 output, no rounding)
        {
            dim3 grid(GG / 128, MT / 128);
            k_gemm_tf32<<<grid, 256, GEMM_SMEM>>>(seq_in, Wih_l, bih_l, xw, MT, GG, HH, 0);
        }
        k_reset<<<(2 * HH * BQ + 255) / 256, 256>>>();
        {
            dim3 grid(HH / 16, BQ / 64);   // (32, 4) = 128 CTAs
            k_lstm_persist<<<grid, 256, PERSIST_SMEM>>>(xw, Whh_l, bhh_l, seq_out);
        }
        const float* tmp_in = seq_out;
        seq_out = (float*)seq_in;
        seq_in  = tmp_in;
    }

    // 5) heads
    k_head<<<(BQ * 560 + 255) / 256, 256>>>(seq_in, W_out, b_out, W_cls, b_cls, out);
}

// round 5
// speedup vs baseline: 4.9757x; 1.2353x over previous
#include <cuda_runtime.h>
#include <math.h>
#include <stdint.h>

// ---------------- problem constants ----------------
#define BQ     256
#define TT     100
#define NFEAT  64
#define VV     32
#define EE     8
#define HH     512
#define NCAT   16
#define NCONT  48
#define INLEN  176
#define GG     2048
#define MT     (BQ*TT)

// persist smem: Bs [512][72] + Ha [2][64][72] + Xs [2][64][68] + Hs [16][68]
#define P_BS_F   (512*72)
#define P_HA_F   (2*64*72)
#define P_XS_F   (2*64*68)
#define P_HS_F   (16*68)
#define PERSIST_SMEM ((P_BS_F + P_HA_F + P_XS_F + P_HS_F) * 4)   // 223,488 B

// GEMM smem: 4 stages x (A 128x20 + W 128x20)
#define GSTAGE_F (128*20)
#define GEMM_SMEM (4 * 2 * GSTAGE_F * 4)   // 81,920 B

// ---------------- scratch ----------------
__device__ float g_feat[MT * INLEN];
__device__ float g_seq0[MT * HH];
__device__ float g_seq1[MT * HH];
__device__ float g_xw  [(size_t)MT * GG];
__device__ float g_WinT[HH * INLEN];
__device__ float g_WihR[2 * GG * HH];
__device__ float g_ht  [2 * HH * BQ];
__device__ unsigned g_count;
__device__ unsigned g_gen;

// ---------------- helpers ----------------
__device__ __forceinline__ unsigned tf32u(float x) {
    unsigned u; asm("cvt.rna.tf32.f32 %0, %1;" : "=r"(u) : "f"(x)); return u;
}
__device__ __forceinline__ float tf32f(float x) { return __uint_as_float(tf32u(x)); }

__device__ __forceinline__ void mma8(float* d, const unsigned* a, const unsigned* b) {
    asm volatile("mma.sync.aligned.m16n8k8.row.col.f32.tf32.tf32.f32 "
                 "{%0,%1,%2,%3}, {%4,%5,%6,%7}, {%8,%9}, {%0,%1,%2,%3};"
                 : "+f"(d[0]), "+f"(d[1]), "+f"(d[2]), "+f"(d[3])
                 : "r"(a[0]), "r"(a[1]), "r"(a[2]), "r"(a[3]), "r"(b[0]), "r"(b[1]));
}

__device__ __forceinline__ void cpasync16(float* smem_dst, const float* gsrc) {
    unsigned s = (unsigned)__cvta_generic_to_shared(smem_dst);
    asm volatile("cp.async.cg.shared.global [%0], [%1], 16;" :: "r"(s), "l"(gsrc));
}
__device__ __forceinline__ void cpcommit() { asm volatile("cp.async.commit_group;" ::: "memory"); }
template<int N> __device__ __forceinline__ void cpwaitN() {
    asm volatile("cp.async.wait_group %0;" :: "n"(N) : "memory");
}

__device__ __forceinline__ float sigm(float x)     { return 1.f / (1.f + __expf(-x)); }
__device__ __forceinline__ float tanhfast(float x) { return 2.f / (1.f + __expf(-2.f * x)) - 1.f; }

// ---------------- small utility kernels ----------------
__global__ void k_transpose_win(const float* __restrict__ Win, float* __restrict__ WinT)
{
    int idx = blockIdx.x * blockDim.x + threadIdx.x;
    if (idx >= INLEN * HH) return;
    int k = idx / HH, n = idx % HH;
    WinT[n * INLEN + k] = tf32f(Win[idx]);
}

__global__ void k_round_wih(const float* __restrict__ W, float* __restrict__ R)
{
    int i = blockIdx.x * blockDim.x + threadIdx.x;
    if (i < 2 * GG * HH) R[i] = tf32f(W[i]);
}

__global__ void k_reset()
{
    int i = blockIdx.x * blockDim.x + threadIdx.x;
    if (i < 2 * HH * BQ) g_ht[i] = 0.f;
    if (i == 0) { g_count = 0; g_gen = 0; }
}

__global__ void k_build_feat(const float* __restrict__ x,
                             const float* __restrict__ mean,
                             const float* __restrict__ scale,
                             const float* __restrict__ emb,
                             float* __restrict__ feat)
{
    int idx = blockIdx.x * blockDim.x + threadIdx.x;
    if (idx >= MT * INLEN) return;
    int c = idx % INLEN;
    int m = idx / INLEN;
    int blk = c / 11, r = c % 11;
    float v;
    if (r < 8) {
        int k  = 4 * blk;
        int xi = (int)x[(size_t)m * NFEAT + k];
        v = emb[((size_t)blk * VV + xi) * EE + r];
    } else {
        int k = 4 * blk + (r - 7);
        v = (x[(size_t)m * NFEAT + k] - mean[k]) / scale[k];
    }
    feat[idx] = tf32f(v);
}

// ---------------- tf32 NT GEMM: 128x128 CTA, 4 warps of 64x64, 4-stage cp.async ----
__device__ __forceinline__ void gemm_load_stage(float* dstA, float* dstW,
                                                const float* A, const float* W,
                                                int bm, int bn, int K, int kc, int tid)
{
    int k0 = kc << 4;
#pragma unroll
    for (int i = 0; i < 4; i++) {
        int e   = tid + i * 128;   // 0..511
        int row = e >> 2;
        int q   = (e & 3) << 2;
        cpasync16(dstA + row * 20 + q, A + (size_t)(bm + row) * K + k0 + q);
    }
#pragma unroll
    for (int i = 0; i < 4; i++) {
        int e   = tid + i * 128;
        int row = e >> 2;
        int q   = (e & 3) << 2;
        cpasync16(dstW + row * 20 + q, W + (size_t)(bn + row) * K + k0 + q);
    }
}

__global__ __launch_bounds__(128, 2)
void k_gemm_tf32(const float* __restrict__ A, const float* __restrict__ W,
                 const float* __restrict__ bias, float* __restrict__ C,
                 int M, int N, int K, int flags)   // bit0: relu, bit1: round out
{
    extern __shared__ float sm[];
    float* As = sm;
    float* Ws = sm + 4 * GSTAGE_F;

    const int tid  = threadIdx.x;
    const int bm   = blockIdx.y * 128;
    const int bn   = blockIdx.x * 128;
    const int lane = tid & 31, warp = tid >> 5;
    const int wm   = (warp & 1) * 64;
    const int wn   = (warp >> 1) * 64;
    const int r    = lane >> 2, cq = lane & 3;
    const int NK   = K >> 4;

    float acc[4][8][4];
#pragma unroll
    for (int mt = 0; mt < 4; mt++)
#pragma unroll
        for (int in = 0; in < 8; in++)
#pragma unroll
            for (int q = 0; q < 4; q++) acc[mt][in][q] = 0.f;

    gemm_load_stage(As, Ws, A, W, bm, bn, K, 0, tid); cpcommit();
    gemm_load_stage(As + GSTAGE_F, Ws + GSTAGE_F, A, W, bm, bn, K, 1, tid); cpcommit();
    gemm_load_stage(As + 2 * GSTAGE_F, Ws + 2 * GSTAGE_F, A, W, bm, bn, K, 2, tid); cpcommit();

    for (int kc = 0; kc < NK; kc++) {
        if      (kc < NK - 2) cpwaitN<2>();
        else if (kc < NK - 1) cpwaitN<1>();
        else                  cpwaitN<0>();
        __syncthreads();
        if (kc + 3 < NK) {
            int s = (kc + 3) & 3;
            gemm_load_stage(As + s * GSTAGE_F, Ws + s * GSTAGE_F, A, W, bm, bn, K, kc + 3, tid);
            cpcommit();
        }
        const float* as = As + (kc & 3) * GSTAGE_F;
        const float* ws = Ws + (kc & 3) * GSTAGE_F;
#pragma unroll
        for (int kk = 0; kk < 16; kk += 8) {
            unsigned a[4][4], b[8][2];
#pragma unroll
            for (int mt = 0; mt < 4; mt++) {
                int m0 = wm + mt * 16;
                a[mt][0] = __float_as_uint(as[(m0 + r    ) * 20 + kk + cq    ]);
                a[mt][1] = __float_as_uint(as[(m0 + r + 8) * 20 + kk + cq    ]);
                a[mt][2] = __float_as_uint(as[(m0 + r    ) * 20 + kk + 4 + cq]);
                a[mt][3] = __float_as_uint(as[(m0 + r + 8) * 20 + kk + 4 + cq]);
            }
#pragma unroll
            for (int in = 0; in < 8; in++) {
                int n0 = wn + in * 8;
                b[in][0] = __float_as_uint(ws[(n0 + r) * 20 + kk + cq    ]);
                b[in][1] = __float_as_uint(ws[(n0 + r) * 20 + kk + 4 + cq]);
            }
#pragma unroll
            for (int mt = 0; mt < 4; mt++)
#pragma unroll
                for (int in = 0; in < 8; in++)
                    mma8(acc[mt][in], a[mt], b[in]);
        }
    }

    const int doRelu  = flags & 1;
    const int doRound = flags & 2;
#pragma unroll
    for (int mt = 0; mt < 4; mt++) {
        int row = bm + wm + mt * 16 + r;
#pragma unroll
        for (int in = 0; in < 8; in++) {
            int col = bn + wn + in * 8 + 2 * cq;
            float2 bv = *(const float2*)(bias + col);
            float v0 = acc[mt][in][0] + bv.x;
            float v1 = acc[mt][in][1] + bv.y;
            float v2 = acc[mt][in][2] + bv.x;
            float v3 = acc[mt][in][3] + bv.y;
            if (doRelu) {
                v0 = fmaxf(v0, 0.f); v1 = fmaxf(v1, 0.f);
                v2 = fmaxf(v2, 0.f); v3 = fmaxf(v3, 0.f);
            }
            if (doRound) { v0 = tf32f(v0); v1 = tf32f(v1); v2 = tf32f(v2); v3 = tf32f(v3); }
            *(float2*)(C + (size_t)row * N + col)       = make_float2(v0, v1);
            *(float2*)(C + (size_t)(row + 8) * N + col) = make_float2(v2, v3);
        }
    }
}

// ---------------- persistent recurrent LSTM layer ----------------
// 128 CTAs = 4 batch-tiles(64) x 32 j-tiles(16). CTA mma tile 64m x 64n,
// 8 warps: 4 tiles of 32x32, 2-way split-K (warps 0-3: k<256, 4-7: k>=256).
// Gates merged in smem; epilogue jj-major; xw for t+1 prefetched pre-barrier.
#define KCH 64
#define NCH 8

__device__ __forceinline__ void load_ha(float* dst, const float* ht_in,
                                        int k0, int m0, int tid)
{
#pragma unroll
    for (int i = 0; i < 4; i++) {
        int s  = tid + i * 256;
        int kk = s >> 4;              // 0..63
        int c4 = (s & 15) << 2;
        cpasync16(dst + kk * 72 + c4, ht_in + (size_t)(k0 + kk) * BQ + m0 + c4);
    }
}

__device__ __forceinline__ void load_xs(float* dst, const float* xw,
                                        int t, int m0, int j0, int tid)
{
#pragma unroll
    for (int i = 0; i < 4; i++) {
        int s   = tid + i * 256;
        int row = s >> 4;             // 0..63
        int q   = (s >> 2) & 3;
        int f4  = (s & 3) << 2;
        cpasync16(dst + row * 68 + q * 16 + f4,
                  xw + ((size_t)(m0 + row) * TT + t) * GG + q * HH + j0 + f4);
    }
}

__global__ __launch_bounds__(256, 1)
void k_lstm_persist(const float* __restrict__ xw, const float* __restrict__ Whh,
                    const float* __restrict__ bhh, float* __restrict__ seq_out)
{
    extern __shared__ float sm[];
    float* Bs = sm;                          // [512][72] Whh slice (tf32)
    float* Ha = sm + P_BS_F;                 // [2][64][72] h chunks (Gs reuses buf 0)
    float* Xs = sm + P_BS_F + P_HA_F;        // [2][64][68] xw tiles
    float* Hs = sm + P_BS_F + P_HA_F + P_XS_F; // [16][68] h staging

    const int tid   = threadIdx.x, lane = tid & 31, warp = tid >> 5;
    const int j0    = blockIdx.x * 16;
    const int m0    = blockIdx.y * 64;
    const int khalf = warp >> 2;
    const int wmw   = (warp & 1) * 32;
    const int wnw   = ((warp >> 1) & 1) * 32;
    const int r     = lane >> 2, cq = lane & 3;
    const int jjt   = tid & 15;              // epilogue: jj-major
    const int mgt   = tid >> 4;              // 0..15

    // one-time Whh slice, gate-interleaved: col n = jj*4+q <-> row q*512+j0+jj
    for (int idx = tid; idx < 64 * 128; idx += 256) {
        int n  = idx & 63;
        int k4 = idx >> 6;
        int jj = n >> 2, q = n & 3;
        float4 v = *(const float4*)(Whh + (size_t)(q * HH + j0 + jj) * HH + k4 * 4);
        Bs[(k4 * 4 + 0) * 72 + n] = tf32f(v.x);
        Bs[(k4 * 4 + 1) * 72 + n] = tf32f(v.y);
        Bs[(k4 * 4 + 2) * 72 + n] = tf32f(v.z);
        Bs[(k4 * 4 + 3) * 72 + n] = tf32f(v.w);
    }
    float bh[4];
#pragma unroll
    for (int q = 0; q < 4; q++) bh[q] = bhh[q * HH + j0 + jjt];
    __syncthreads();

    float cst[4] = {0.f, 0.f, 0.f, 0.f};     // cell state: (m = mgt+16*it, j = j0+jjt)

    // prologue for t=0: Xs then h chunk 0 (separate groups)
    load_xs(Xs, xw, 0, m0, j0, tid); cpcommit();
    load_ha(Ha, g_ht, 0, m0, tid);   cpcommit();

    for (int t = 0; t < TT; t++) {
        const int pin = t & 1;
        const float* ht_in  = g_ht + (size_t)pin * (HH * BQ);
        float*       ht_out = g_ht + (size_t)(pin ^ 1) * (HH * BQ);

        float acc[2][4][4];
#pragma unroll
        for (int mt = 0; mt < 2; mt++)
#pragma unroll
            for (int in = 0; in < 4; in++)
#pragma unroll
                for (int q = 0; q < 4; q++) acc[mt][in][q] = 0.f;

        for (int kc = 0; kc < NCH; kc++) {
            cpwaitN<0>();
            __syncthreads();
            if (kc + 1 < NCH) {
                load_ha(Ha + ((kc + 1) & 1) * (64 * 72), ht_in, (kc + 1) * KCH, m0, tid);
                cpcommit();
            }
            if ((kc >> 2) == khalf) {
                const float* hb = Ha + (kc & 1) * (64 * 72);
                const int kgb = kc * KCH;
#pragma unroll
                for (int kk = 0; kk < KCH; kk += 8) {
                    unsigned a[2][4];
#pragma unroll
                    for (int mt = 0; mt < 2; mt++) {
                        int mrow = wmw + mt * 16 + r;
                        a[mt][0] = __float_as_uint(hb[(kk + cq    ) * 72 + mrow    ]);
                        a[mt][1] = __float_as_uint(hb[(kk + cq    ) * 72 + mrow + 8]);
                        a[mt][2] = __float_as_uint(hb[(kk + 4 + cq) * 72 + mrow    ]);
                        a[mt][3] = __float_as_uint(hb[(kk + 4 + cq) * 72 + mrow + 8]);
                    }
                    const int kg = kgb + kk;
#pragma unroll
                    for (int in = 0; in < 4; in++) {
                        unsigned b[2];
                        b[0] = __float_as_uint(Bs[(kg + cq    ) * 72 + wnw + in * 8 + r]);
                        b[1] = __float_as_uint(Bs[(kg + 4 + cq) * 72 + wnw + in * 8 + r]);
                        mma8(acc[0][in], a[0], b);
                        mma8(acc[1][in], a[1], b);
                    }
                }
            }
        }
        __syncthreads();    // all chunk compute done; Ha buf0 free -> Gs

        float* Gs = Ha;     // [64][72] gate merge buffer
        if (khalf == 0) {
#pragma unroll
            for (int mt = 0; mt < 2; mt++) {
                int row = wmw + mt * 16 + r;
#pragma unroll
                for (int in = 0; in < 4; in++) {
                    int col = wnw + in * 8 + 2 * cq;
                    *(float2*)&Gs[row * 72 + col]       = make_float2(acc[mt][in][0], acc[mt][in][1]);
                    *(float2*)&Gs[(row + 8) * 72 + col] = make_float2(acc[mt][in][2], acc[mt][in][3]);
                }
            }
        }
        __syncthreads();
        if (khalf == 1) {
#pragma unroll
            for (int mt = 0; mt < 2; mt++) {
                int row = wmw + mt * 16 + r;
#pragma unroll
                for (int in = 0; in < 4; in++) {
                    int col = wnw + in * 8 + 2 * cq;
                    float2 p0 = *(float2*)&Gs[row * 72 + col];
                    float2 p1 = *(float2*)&Gs[(row + 8) * 72 + col];
                    p0.x += acc[mt][in][0]; p0.y += acc[mt][in][1];
                    p1.x += acc[mt][in][2]; p1.y += acc[mt][in][3];
                    *(float2*)&Gs[row * 72 + col]       = p0;
                    *(float2*)&Gs[(row + 8) * 72 + col] = p1;
                }
            }
        }
        __syncthreads();

        // prefetch next step's xw tile (independent of h / barrier)
        if (t + 1 < TT) { load_xs(Xs + ((t + 1) & 1) * (64 * 68), xw, t + 1, m0, j0, tid); cpcommit(); }

        // epilogue: thread (jjt, m = mgt+16*it)
        const float* xs = Xs + (t & 1) * (64 * 68);
#pragma unroll
        for (int it = 0; it < 4; it++) {
            int m = mgt + it * 16;
            float4 g = *(const float4*)&Gs[m * 72 + jjt * 4];
            float gi = g.x + xs[m * 68 +      jjt] + bh[0];
            float gf = g.y + xs[m * 68 + 16 + jjt] + bh[1];
            float gg = g.z + xs[m * 68 + 32 + jjt] + bh[2];
            float go = g.w + xs[m * 68 + 48 + jjt] + bh[3];
            float iv = sigm(gi), fv = sigm(gf);
            float gv = tanhfast(gg), ov = sigm(go);
            float cv = fv * cst[it] + iv * gv;
            cst[it] = cv;
            float hv = ov * tanhfast(cv);
            Hs[jjt * 68 + m] = tf32f(hv);
            seq_out[((size_t)(m0 + m) * TT + t) * HH + j0 + jjt] = tf32f(fmaxf(hv, 0.f));
        }
        __syncthreads();
        // cooperative coalesced ht_out store
        {
            int j  = tid >> 4;            // 0..15
            int ms = (tid & 15) << 2;     // 0..60
            float4 hv4 = *(const float4*)&Hs[j * 68 + ms];
            *(float4*)&ht_out[(size_t)(j0 + j) * BQ + m0 + ms] = hv4;
        }

        // grid barrier
        __threadfence();
        __syncthreads();
        if (tid == 0) {
            atomicAdd(&g_count, 1u);
            if (blockIdx.x == 0 && blockIdx.y == 0) {
                while (*(volatile unsigned*)&g_count < 128u * (unsigned)(t + 1)) { }
                __threadfence();
                *(volatile unsigned*)&g_gen = (unsigned)(t + 1);
            } else {
                while (*(volatile unsigned*)&g_gen < (unsigned)(t + 1)) { }
                __threadfence();
            }
        }
        __syncthreads();

        // prologue h chunk 0 for t+1
        if (t + 1 < TT) {
            load_ha(Ha, g_ht + (size_t)((t + 1) & 1) * (HH * BQ), 0, m0, tid);
            cpcommit();
        }
    }
}

// ---------------- heads ----------------
__global__ void k_head(const float* __restrict__ seq,
                       const float* __restrict__ W_out, const float* __restrict__ b_out,
                       const float* __restrict__ W_cls, const float* __restrict__ b_cls,
                       float* __restrict__ out)
{
    int idx = blockIdx.x * blockDim.x + threadIdx.x;
    if (idx >= BQ * 560) return;
    int b = idx / 560, c = idx % 560;
    const float* last = seq + ((size_t)b * TT + (TT - 1)) * HH;
    if (c < NCONT) {
        float s = b_out[c];
#pragma unroll 4
        for (int k = 0; k < HH; k++) s += last[k] * W_out[k * NCONT + c];
        out[b * NCONT + c] = s;
    } else {
        int cc = c - NCONT;
        int n = cc >> 5, v = cc & 31;
        float s = b_cls[n * VV + v];
        const float* w = W_cls + (size_t)n * HH * VV + v;
#pragma unroll 4
        for (int k = 0; k < HH; k++) s += last[k] * w[k * VV];
        out[BQ * NCONT + (size_t)b * (NCAT * VV) + cc] = s;
    }
}

// ---------------- launch ----------------
extern "C" void kernel_launch(void* const* d_in, const int* in_sizes, int n_in,
                              void* d_out, int out_size)
{
    const float* x      = (const float*)d_in[0];
    const float* smean  = (const float*)d_in[1];
    const float* sscale = (const float*)d_in[2];
    const float* emb    = (const float*)d_in[3];
    const float* W_in   = (const float*)d_in[4];
    const float* b_in   = (const float*)d_in[5];
    const float* Wih    = (const float*)d_in[6];
    const float* Whh    = (const float*)d_in[7];
    const float* bih    = (const float*)d_in[8];
    const float* bhh    = (const float*)d_in[9];
    const float* W_out  = (const float*)d_in[10];
    const float* b_out  = (const float*)d_in[11];
    const float* W_cls  = (const float*)d_in[12];
    const float* b_cls  = (const float*)d_in[13];
    float* out = (float*)d_out;

    float *feat, *seq0, *seq1, *xw, *winT, *wihR;
    cudaGetSymbolAddress((void**)&feat, g_feat);
    cudaGetSymbolAddress((void**)&seq0, g_seq0);
    cudaGetSymbolAddress((void**)&seq1, g_seq1);
    cudaGetSymbolAddress((void**)&xw,   g_xw);
    cudaGetSymbolAddress((void**)&winT, g_WinT);
    cudaGetSymbolAddress((void**)&wihR, g_WihR);

    cudaFuncSetAttribute(k_lstm_persist, cudaFuncAttributeMaxDynamicSharedMemorySize,
                         PERSIST_SMEM);
    cudaFuncSetAttribute(k_gemm_tf32, cudaFuncAttributeMaxDynamicSharedMemorySize,
                         GEMM_SMEM);

    k_transpose_win<<<(INLEN * HH + 255) / 256, 256>>>(W_in, winT);
    k_round_wih<<<(2 * GG * HH + 255) / 256, 256>>>(Wih, wihR);
    k_build_feat<<<(MT * INLEN + 255) / 256, 256>>>(x, smean, sscale, emb, feat);

    {
        dim3 grid(HH / 128, MT / 128);
        k_gemm_tf32<<<grid, 128, GEMM_SMEM>>>(feat, winT, b_in, seq0, MT, HH, INLEN, 3);
    }

    const float* seq_in  = seq0;
    float*       seq_out = seq1;
    for (int l = 0; l < 2; l++) {
        const float* Wih_l = wihR + (size_t)l * GG * HH;
        const float* Whh_l = Whh  + (size_t)l * GG * HH;
        const float* bih_l = bih  + (size_t)l * GG;
        const float* bhh_l = bhh  + (size_t)l * GG;

        {
            dim3 grid(GG / 128, MT / 128);
            k_gemm_tf32<<<grid, 128, GEMM_SMEM>>>(seq_in, Wih_l, bih_l, xw, MT, GG, HH, 0);
        }
        k_reset<<<(2 * HH * BQ + 255) / 256, 256>>>();
        {
            dim3 grid(HH / 16, BQ / 64);   // (32, 4) = 128 CTAs
            k_lstm_persist<<<grid, 256, PERSIST_SMEM>>>(xw, Whh_l, bhh_l, seq_out);
        }
        const float* tmp_in = seq_out;
        seq_out = (float*)seq_in;
        seq_in  = tmp_in;
    }

    k_head<<<(BQ * 560 + 255) / 256, 256>>>(seq_in, W_out, b_out, W_cls, b_cls, out);
}

// round 6
// speedup vs baseline: 4.9885x; 1.0026x over previous
#include <cuda_runtime.h>
#include <math.h>
#include <stdint.h>

// ---------------- problem constants ----------------
#define BQ     256
#define TT     100
#define NFEAT  64
#define VV     32
#define EE     8
#define HH     512
#define NCAT   16
#define NCONT  48
#define INLEN  176
#define GG     2048
#define MT     (BQ*TT)

// persist smem: Bs [64][516] + Ha [3][64][68] + Xs [2][64][68]
#define P_BS_F   (64*516)
#define P_HA_F   (3*64*68)
#define P_XS_F   (2*64*68)
#define PERSIST_SMEM ((P_BS_F + P_HA_F + P_XS_F) * 4)   // 219,136 B

// GEMM smem: 3 stages x (A 128x36 + W 128x36)
#define ASTAGE_F (128*36)
#define GEMM_SMEM (3 * 2 * ASTAGE_F * 4)                 // 110,592 B

// ---------------- scratch (padded for cp.async tail overreach) ----------------
__device__ float g_feat[MT * INLEN + 64];
__device__ float g_seq0[MT * HH + 64];
__device__ float g_seq1[MT * HH + 64];
__device__ float g_xw  [(size_t)MT * GG];
__device__ float g_WinT[HH * INLEN + 64];
__device__ float g_WihR[2 * GG * HH];
__device__ float g_WhhR[2 * GG * HH];
__device__ float g_ht  [2 * BQ * HH];     // m-major h state, double buffered
__device__ unsigned g_count;
__device__ unsigned g_gen;

// ---------------- helpers ----------------
__device__ __forceinline__ unsigned tf32u(float x) {
    unsigned u; asm("cvt.rna.tf32.f32 %0, %1;" : "=r"(u) : "f"(x)); return u;
}
__device__ __forceinline__ float tf32f(float x) { return __uint_as_float(tf32u(x)); }

__device__ __forceinline__ void mma8(float* d, const unsigned* a, const unsigned* b) {
    asm volatile("mma.sync.aligned.m16n8k8.row.col.f32.tf32.tf32.f32 "
                 "{%0,%1,%2,%3}, {%4,%5,%6,%7}, {%8,%9}, {%0,%1,%2,%3};"
                 : "+f"(d[0]), "+f"(d[1]), "+f"(d[2]), "+f"(d[3])
                 : "r"(a[0]), "r"(a[1]), "r"(a[2]), "r"(a[3]), "r"(b[0]), "r"(b[1]));
}

__device__ __forceinline__ void ldsm4(unsigned& r0, unsigned& r1, unsigned& r2, unsigned& r3,
                                      unsigned addr) {
    asm volatile("ldmatrix.sync.aligned.m8n8.x4.shared.b16 {%0,%1,%2,%3}, [%4];"
                 : "=r"(r0), "=r"(r1), "=r"(r2), "=r"(r3) : "r"(addr));
}

__device__ __forceinline__ void cpasync16(float* smem_dst, const float* gsrc) {
    unsigned s = (unsigned)__cvta_generic_to_shared(smem_dst);
    asm volatile("cp.async.cg.shared.global [%0], [%1], 16;" :: "r"(s), "l"(gsrc));
}
__device__ __forceinline__ void cpcommit() { asm volatile("cp.async.commit_group;" ::: "memory"); }
template<int N> __device__ __forceinline__ void cpwaitN() {
    asm volatile("cp.async.wait_group %0;" :: "n"(N) : "memory");
}

__device__ __forceinline__ float sigm(float x)     { return 1.f / (1.f + __expf(-x)); }
__device__ __forceinline__ float tanhfast(float x) { return 2.f / (1.f + __expf(-2.f * x)) - 1.f; }

// ---------------- small utility kernels ----------------
__global__ void k_transpose_win(const float* __restrict__ Win, float* __restrict__ WinT)
{
    int idx = blockIdx.x * blockDim.x + threadIdx.x;
    if (idx >= INLEN * HH) return;
    int k = idx / HH, n = idx % HH;
    WinT[n * INLEN + k] = tf32f(Win[idx]);
}

__global__ void k_round2(const float* __restrict__ A, float* __restrict__ RA,
                         const float* __restrict__ B, float* __restrict__ RB)
{
    int i = blockIdx.x * blockDim.x + threadIdx.x;
    if (i < 2 * GG * HH) { RA[i] = tf32f(A[i]); RB[i] = tf32f(B[i]); }
}

__global__ void k_reset()
{
    int i = blockIdx.x * blockDim.x + threadIdx.x;
    if (i < 2 * BQ * HH) g_ht[i] = 0.f;
    if (i == 0) { g_count = 0; g_gen = 0; }
}

__global__ void k_build_feat(const float* __restrict__ x,
                             const float* __restrict__ mean,
                             const float* __restrict__ scale,
                             const float* __restrict__ emb,
                             float* __restrict__ feat)
{
    int idx = blockIdx.x * blockDim.x + threadIdx.x;
    if (idx >= MT * INLEN) return;
    int c = idx % INLEN;
    int m = idx / INLEN;
    int blk = c / 11, r = c % 11;
    float v;
    if (r < 8) {
        int k  = 4 * blk;
        int xi = (int)x[(size_t)m * NFEAT + k];
        v = emb[((size_t)blk * VV + xi) * EE + r];
    } else {
        int k = 4 * blk + (r - 7);
        v = (x[(size_t)m * NFEAT + k] - mean[k]) / scale[k];
    }
    feat[idx] = tf32f(v);
}

// ---------------- tf32 NT GEMM: 128x128 CTA, 8 warps of 32x64, BK=32, LDSM ----
__device__ __forceinline__ void gemm_load_stage(float* dstA, float* dstW,
                                                const float* A, const float* W,
                                                int bm, int bn, int K, int k0, int tid)
{
#pragma unroll
    for (int i = 0; i < 4; i++) {
        int e   = tid + i * 256;      // 0..1023
        int row = e >> 3;             // 0..127
        int q   = (e & 7) << 2;       // 0..28
        cpasync16(dstA + row * 36 + q, A + (size_t)(bm + row) * K + k0 + q);
    }
#pragma unroll
    for (int i = 0; i < 4; i++) {
        int e   = tid + i * 256;
        int row = e >> 3;
        int q   = (e & 7) << 2;
        cpasync16(dstW + row * 36 + q, W + (size_t)(bn + row) * K + k0 + q);
    }
}

__global__ __launch_bounds__(256, 2)
void k_gemm_tf32(const float* __restrict__ A, const float* __restrict__ W,
                 const float* __restrict__ bias, float* __restrict__ C,
                 int M, int N, int K, int flags)   // bit0: relu, bit1: round out
{
    extern __shared__ float sm[];
    float* As = sm;                     // [3][128*36]
    float* Ws = sm + 3 * ASTAGE_F;

    const int tid  = threadIdx.x;
    const int bm   = blockIdx.y * 128;
    const int bn   = blockIdx.x * 128;
    const int lane = tid & 31, warp = tid >> 5;
    const int wm   = (warp & 3) * 32;   // 4 m-warps, tile 32
    const int wn   = (warp >> 2) * 64;  // 2 n-warps, tile 64
    const int r    = lane >> 2, cq = lane & 3;
    const int NK   = (K + 31) >> 5;

    const unsigned sb = (unsigned)__cvta_generic_to_shared(sm);
    // per-thread ldmatrix byte offsets (within stage)
    const int arow = lane & 15;
    const int kA   = (lane & 16) ? 4 : 0;
    const int brow = (lane & 7) + ((lane & 16) ? 8 : 0);
    const int kB   = (lane & 8) ? 4 : 0;
    const unsigned aoff = ((wm + arow) * 36 + kA) * 4;
    const unsigned boff = ((wn + brow) * 36 + kB) * 4;

    float acc[2][8][4];
#pragma unroll
    for (int mt = 0; mt < 2; mt++)
#pragma unroll
        for (int in = 0; in < 8; in++)
#pragma unroll
            for (int q = 0; q < 4; q++) acc[mt][in][q] = 0.f;

    gemm_load_stage(As, Ws, A, W, bm, bn, K, 0, tid); cpcommit();
    if (NK > 1) { gemm_load_stage(As + ASTAGE_F, Ws + ASTAGE_F, A, W, bm, bn, K, 32, tid); }
    cpcommit();

    for (int kc = 0; kc < NK; kc++) {
        if (kc + 1 < NK) cpwaitN<1>(); else cpwaitN<0>();
        __syncthreads();
        if (kc + 2 < NK) {
            int s = (kc + 2) % 3;
            gemm_load_stage(As + s * ASTAGE_F, Ws + s * ASTAGE_F, A, W, bm, bn, K,
                            (kc + 2) << 5, tid);
            cpcommit();
        }
        const unsigned asb = sb + ((kc % 3) * ASTAGE_F) * 4;
        const unsigned wsb = sb + ((3 + kc % 3) * ASTAGE_F) * 4;
        const int kmax = K - (kc << 5);
#pragma unroll
        for (int kk = 0; kk < 32; kk += 8) {
            if (kk < kmax) {
                unsigned a[2][4], b[8][2];
#pragma unroll
                for (int mt = 0; mt < 2; mt++)
                    ldsm4(a[mt][0], a[mt][1], a[mt][2], a[mt][3],
                          asb + aoff + (mt * 16 * 36 + kk) * 4);
#pragma unroll
                for (int p = 0; p < 4; p++) {
                    unsigned t0, t1, t2, t3;
                    ldsm4(t0, t1, t2, t3, wsb + boff + (p * 16 * 36 + kk) * 4);
                    b[2 * p][0] = t0; b[2 * p][1] = t1;
                    b[2 * p + 1][0] = t2; b[2 * p + 1][1] = t3;
                }
#pragma unroll
                for (int mt = 0; mt < 2; mt++)
#pragma unroll
                    for (int in = 0; in < 8; in++)
                        mma8(acc[mt][in], a[mt], b[in]);
            }
        }
    }

    const int doRelu  = flags & 1;
    const int doRound = flags & 2;
#pragma unroll
    for (int mt = 0; mt < 2; mt++) {
        int row = bm + wm + mt * 16 + r;
#pragma unroll
        for (int in = 0; in < 8; in++) {
            int col = bn + wn + in * 8 + 2 * cq;
            float2 bv = *(const float2*)(bias + col);
            float v0 = acc[mt][in][0] + bv.x;
            float v1 = acc[mt][in][1] + bv.y;
            float v2 = acc[mt][in][2] + bv.x;
            float v3 = acc[mt][in][3] + bv.y;
            if (doRelu) {
                v0 = fmaxf(v0, 0.f); v1 = fmaxf(v1, 0.f);
                v2 = fmaxf(v2, 0.f); v3 = fmaxf(v3, 0.f);
            }
            if (doRound) { v0 = tf32f(v0); v1 = tf32f(v1); v2 = tf32f(v2); v3 = tf32f(v3); }
            *(float2*)(C + (size_t)row * N + col)       = make_float2(v0, v1);
            *(float2*)(C + (size_t)(row + 8) * N + col) = make_float2(v2, v3);
        }
    }
}

// ---------------- persistent recurrent LSTM layer ----------------
// 128 CTAs = 4 batch-tiles(64) x 32 j-tiles(16). CTA mma tile 64m x 64n(gates),
// 8 warps: 2x2 tiles of 32x32, 2-way split-K. LDSM operand loads.
#define KCH 64
#define NCH 8
#define NCTA_PERSIST 128

__device__ __forceinline__ void load_ha(float* dst, const float* ht_in,
                                        int k0, int m0, int tid)
{
#pragma unroll
    for (int i = 0; i < 4; i++) {
        int s   = tid + i * 256;      // 0..1023
        int row = s >> 4;             // m: 0..63
        int c4  = (s & 15) << 2;      // k: 0..60
        cpasync16(dst + row * 68 + c4, ht_in + (size_t)(m0 + row) * HH + k0 + c4);
    }
}

__device__ __forceinline__ void load_xs(float* dst, const float* xw,
                                        int t, int m0, int j0, int tid)
{
#pragma unroll
    for (int i = 0; i < 4; i++) {
        int s   = tid + i * 256;
        int row = s >> 4;             // 0..63
        int q   = (s >> 2) & 3;
        int f4  = (s & 3) << 2;
        cpasync16(dst + row * 68 + q * 16 + f4,
                  xw + ((size_t)(m0 + row) * TT + t) * GG + q * HH + j0 + f4);
    }
}

__global__ __launch_bounds__(256, 1)
void k_lstm_persist(const float* __restrict__ xw, const float* __restrict__ WhhR,
                    const float* __restrict__ bhh, float* __restrict__ seq_out)
{
    extern __shared__ float sm[];
    float* Bs = sm;                       // [64][516] Whh slice (tf32, [n][k])
    float* Ha = sm + P_BS_F;              // [3][64][68] h chunks ([m][k])
    float* Xs = sm + P_BS_F + P_HA_F;     // [2][64][68] xw tiles

    const int tid   = threadIdx.x, lane = tid & 31, warp = tid >> 5;
    const int j0    = blockIdx.x * 16;
    const int m0    = blockIdx.y * 64;
    const int khalf = warp >> 2;
    const int wmw   = (warp & 1) * 32;
    const int wnw   = ((warp >> 1) & 1) * 32;
    const int r     = lane >> 2, cq = lane & 3;
    const int jjt   = tid & 15;
    const int mgt   = tid >> 4;

    const unsigned sb   = (unsigned)__cvta_generic_to_shared(sm);
    const unsigned sbHa = sb + P_BS_F * 4;
    // ldmatrix per-thread offsets
    const int arow = lane & 15;
    const int kA   = (lane & 16) ? 4 : 0;
    const int brow = (lane & 7) + ((lane & 16) ? 8 : 0);
    const int kB   = (lane & 8) ? 4 : 0;
    const unsigned aoff = ((wmw + arow) * 68 + kA) * 4;
    const unsigned boff = ((wnw + brow) * 516 + kB) * 4;

    // one-time Bs load via cp.async: row n = jj*4+q <- WhhR row q*512+j0+jj, full K
    {
#pragma unroll
        for (int i = 0; i < 32; i++) {
            int s  = tid + i * 256;       // 0..8191
            int n  = s >> 7;              // 0..63
            int c4 = (s & 127) << 2;      // 0..508
            int jj = n >> 2, q = n & 3;
            cpasync16(Bs + n * 516 + c4, WhhR + (size_t)(q * HH + j0 + jj) * HH + c4);
        }
        cpcommit();
    }
    float bh[4];
#pragma unroll
    for (int q = 0; q < 4; q++) bh[q] = bhh[q * HH + j0 + jjt];

    float cst[4] = {0.f, 0.f, 0.f, 0.f};

    // prologue t=0
    load_xs(Xs, xw, 0, m0, j0, tid);  cpcommit();
    load_ha(Ha, g_ht, 0, m0, tid);    cpcommit();
    load_ha(Ha + 64 * 68, g_ht, KCH, m0, tid); cpcommit();

    for (int t = 0; t < TT; t++) {
        const int pin = t & 1;
        const float* ht_in  = g_ht + (size_t)pin * (BQ * HH);
        float*       ht_out = g_ht + (size_t)(pin ^ 1) * (BQ * HH);

        float acc[2][4][4];
#pragma unroll
        for (int mt = 0; mt < 2; mt++)
#pragma unroll
            for (int in = 0; in < 4; in++)
#pragma unroll
                for (int q = 0; q < 4; q++) acc[mt][in][q] = 0.f;

        for (int kc = 0; kc < NCH; kc++) {
            if (kc + 1 < NCH) cpwaitN<1>(); else cpwaitN<0>();
            __syncthreads();
            if (kc + 2 < NCH) {
                load_ha(Ha + ((kc + 2) % 3) * (64 * 68), ht_in, (kc + 2) * KCH, m0, tid);
                cpcommit();
            }
            if ((kc >> 2) == khalf) {
                const unsigned hb = sbHa + ((kc % 3) * 64 * 68) * 4;
                const int kg0 = kc * KCH;
#pragma unroll
                for (int kk = 0; kk < KCH; kk += 8) {
                    unsigned a[2][4];
#pragma unroll
                    for (int mt = 0; mt < 2; mt++)
                        ldsm4(a[mt][0], a[mt][1], a[mt][2], a[mt][3],
                              hb + aoff + (mt * 16 * 68 + kk) * 4);
                    unsigned b[4][2];
#pragma unroll
                    for (int p = 0; p < 2; p++) {
                        unsigned t0, t1, t2, t3;
                        ldsm4(t0, t1, t2, t3,
                              sb + boff + (p * 16 * 516 + kg0 + kk) * 4);
                        b[2 * p][0] = t0; b[2 * p][1] = t1;
                        b[2 * p + 1][0] = t2; b[2 * p + 1][1] = t3;
                    }
#pragma unroll
                    for (int mt = 0; mt < 2; mt++)
#pragma unroll
                        for (int in = 0; in < 4; in++)
                            mma8(acc[mt][in], a[mt], b[in]);
                }
            }
        }
        __syncthreads();   // all compute done; Ha bufs 0/1 become Gs buffers

        // split-K partials to two disjoint Gs regions (stride 68)
        float* Gs = Ha + khalf * (64 * 68);
#pragma unroll
        for (int mt = 0; mt < 2; mt++) {
            int row = wmw + mt * 16 + r;
#pragma unroll
            for (int in = 0; in < 4; in++) {
                int col = wnw + in * 8 + 2 * cq;
                *(float2*)&Gs[row * 68 + col]       = make_float2(acc[mt][in][0], acc[mt][in][1]);
                *(float2*)&Gs[(row + 8) * 68 + col] = make_float2(acc[mt][in][2], acc[mt][in][3]);
            }
        }
        __syncthreads();

        // prefetch next step's xw tile
        if (t + 1 < TT) { load_xs(Xs + ((t + 1) & 1) * (64 * 68), xw, t + 1, m0, j0, tid); cpcommit(); }

        // epilogue: thread (jjt, m = mgt+16*it)
        const float* xs = Xs + (t & 1) * (64 * 68);
        const float* GsA = Ha;
        const float* GsB = Ha + 64 * 68;
#pragma unroll
        for (int it = 0; it < 4; it++) {
            int m = mgt + it * 16;
            float4 ga = *(const float4*)&GsA[m * 68 + jjt * 4];
            float4 gb = *(const float4*)&GsB[m * 68 + jjt * 4];
            float gi = ga.x + gb.x + xs[m * 68 +      jjt] + bh[0];
            float gf = ga.y + gb.y + xs[m * 68 + 16 + jjt] + bh[1];
            float gg = ga.z + gb.z + xs[m * 68 + 32 + jjt] + bh[2];
            float go = ga.w + gb.w + xs[m * 68 + 48 + jjt] + bh[3];
            float iv = sigm(gi), fv = sigm(gf);
            float gv = tanhfast(gg), ov = sigm(go);
            float cv = fv * cst[it] + iv * gv;
            cst[it] = cv;
            float hv = ov * tanhfast(cv);
            ht_out[(size_t)(m0 + m) * HH + j0 + jjt] = tf32f(hv);
            seq_out[((size_t)(m0 + m) * TT + t) * HH + j0 + jjt] = tf32f(fmaxf(hv, 0.f));
        }

        // grid barrier
        __threadfence();
        __syncthreads();
        if (tid == 0) {
            atomicAdd(&g_count, 1u);
            if (blockIdx.x == 0 && blockIdx.y == 0) {
                while (*(volatile unsigned*)&g_count < (unsigned)NCTA_PERSIST * (unsigned)(t + 1)) { }
                __threadfence();
                *(volatile unsigned*)&g_gen = (unsigned)(t + 1);
            } else {
                while (*(volatile unsigned*)&g_gen < (unsigned)(t + 1)) { }
                __threadfence();
            }
        }
        __syncthreads();

        // prologue h chunks 0,1 for t+1
        if (t + 1 < TT) {
            const float* hin2 = g_ht + (size_t)((t + 1) & 1) * (BQ * HH);
            load_ha(Ha, hin2, 0, m0, tid);            cpcommit();
            load_ha(Ha + 64 * 68, hin2, KCH, m0, tid); cpcommit();
        }
    }
}

// ---------------- heads ----------------
__global__ void k_head(const float* __restrict__ seq,
                       const float* __restrict__ W_out, const float* __restrict__ b_out,
                       const float* __restrict__ W_cls, const float* __restrict__ b_cls,
                       float* __restrict__ out)
{
    int idx = blockIdx.x * blockDim.x + threadIdx.x;
    if (idx >= BQ * 560) return;
    int b = idx / 560, c = idx % 560;
    const float* last = seq + ((size_t)b * TT + (TT - 1)) * HH;
    if (c < NCONT) {
        float s = b_out[c];
#pragma unroll 4
        for (int k = 0; k < HH; k++) s += last[k] * W_out[k * NCONT + c];
        out[b * NCONT + c] = s;
    } else {
        int cc = c - NCONT;
        int n = cc >> 5, v = cc & 31;
        float s = b_cls[n * VV + v];
        const float* w = W_cls + (size_t)n * HH * VV + v;
#pragma unroll 4
        for (int k = 0; k < HH; k++) s += last[k] * w[k * VV];
        out[BQ * NCONT + (size_t)b * (NCAT * VV) + cc] = s;
    }
}

// ---------------- launch ----------------
extern "C" void kernel_launch(void* const* d_in, const int* in_sizes, int n_in,
                              void* d_out, int out_size)
{
    const float* x      = (const float*)d_in[0];
    const float* smean  = (const float*)d_in[1];
    const float* sscale = (const float*)d_in[2];
    const float* emb    = (const float*)d_in[3];
    const float* W_in   = (const float*)d_in[4];
    const float* b_in   = (const float*)d_in[5];
    const float* Wih    = (const float*)d_in[6];
    const float* Whh    = (const float*)d_in[7];
    const float* bih    = (const float*)d_in[8];
    const float* bhh    = (const float*)d_in[9];
    const float* W_out  = (const float*)d_in[10];
    const float* b_out  = (const float*)d_in[11];
    const float* W_cls  = (const float*)d_in[12];
    const float* b_cls  = (const float*)d_in[13];
    float* out = (float*)d_out;

    float *feat, *seq0, *seq1, *xw, *winT, *wihR, *whhR;
    cudaGetSymbolAddress((void**)&feat, g_feat);
    cudaGetSymbolAddress((void**)&seq0, g_seq0);
    cudaGetSymbolAddress((void**)&seq1, g_seq1);
    cudaGetSymbolAddress((void**)&xw,   g_xw);
    cudaGetSymbolAddress((void**)&winT, g_WinT);
    cudaGetSymbolAddress((void**)&wihR, g_WihR);
    cudaGetSymbolAddress((void**)&whhR, g_WhhR);

    cudaFuncSetAttribute(k_lstm_persist, cudaFuncAttributeMaxDynamicSharedMemorySize,
                         PERSIST_SMEM);
    cudaFuncSetAttribute(k_gemm_tf32, cudaFuncAttributeMaxDynamicSharedMemorySize,
                         GEMM_SMEM);

    k_transpose_win<<<(INLEN * HH + 255) / 256, 256>>>(W_in, winT);
    k_round2<<<(2 * GG * HH + 255) / 256, 256>>>(Wih, wihR, Whh, whhR);
    k_build_feat<<<(MT * INLEN + 255) / 256, 256>>>(x, smean, sscale, emb, feat);

    {
        dim3 grid(HH / 128, MT / 128);
        k_gemm_tf32<<<grid, 256, GEMM_SMEM>>>(feat, winT, b_in, seq0, MT, HH, INLEN, 3);
    }

    const float* seq_in  = seq0;
    float*       seq_out = seq1;
    for (int l = 0; l < 2; l++) {
        const float* Wih_l = wihR + (size_t)l * GG * HH;
        const float* Whh_l = whhR + (size_t)l * GG * HH;
        const float* bih_l = bih  + (size_t)l * GG;
        const float* bhh_l = bhh  + (size_t)l * GG;

        {
            dim3 grid(GG / 128, MT / 128);
            k_gemm_tf32<<<grid, 256, GEMM_SMEM>>>(seq_in, Wih_l, bih_l, xw, MT, GG, HH, 0);
        }
        k_reset<<<(2 * BQ * HH + 255) / 256, 256>>>();
        {
            dim3 grid(HH / 16, BQ / 64);   // (32, 4) = 128 CTAs
            k_lstm_persist<<<grid, 256, PERSIST_SMEM>>>(xw, Whh_l, bhh_l, seq_out);
        }
        const float* tmp_in = seq_out;
        seq_out = (float*)seq_in;
        seq_in  = tmp_in;
    }

    k_head<<<(BQ * 560 + 255) / 256, 256>>>(seq_in, W_out, b_out, W_cls, b_cls, out);
}

// round 8
// speedup vs baseline: 6.4716x; 1.2973x over previous
#include <cuda_runtime.h>
#include <cuda_fp16.h>
#include <math.h>
#include <stdint.h>

// ---------------- problem constants ----------------
#define BQ     256
#define TT     100
#define NFEAT  64
#define VV     32
#define EE     8
#define HH     512
#define NCAT   16
#define NCONT  48
#define INLEN  176
#define INP    192        // padded K for input projection
#define GG     2048
#define MT     (BQ*TT)

// persist smem (bytes): Bs half[64][520] + Ha half[3][64][72] + Xs f32[2][64][68] + Gs f32[2][64][68]
#define P_BS_B   (64*520*2)                 // 66,560
#define P_HA_B   (3*64*72*2)                // 27,648
#define P_XS_B   (2*64*68*4)                // 34,816
#define P_GS_B   (2*64*68*4)                // 34,816
#define P_HA_OFF (P_BS_B)
#define P_XS_OFF (P_BS_B + P_HA_B)
#define P_GS_OFF (P_BS_B + P_HA_B + P_XS_B)
#define PERSIST_SMEM (P_BS_B + P_HA_B + P_XS_B + P_GS_B)   // 163,840 B

// GEMM smem: 3 stages x (A 128x40 + W 128x40) halves
#define ASTG_H   (128*40)
#define ASTG_B   (ASTG_H*2)                 // 10,240 B
#define GEMM_SMEM (3 * 2 * ASTG_B)          // 61,440 B

// ---------------- scratch ----------------
__device__ __half g_feat[MT * INP + 64];
__device__ __half g_seq0[MT * HH + 64];
__device__ __half g_seq1[MT * HH + 64];
__device__ float  g_xw  [(size_t)MT * GG];
__device__ __half g_WinT[HH * INP + 64];
__device__ __half g_WihR[2 * GG * HH];
__device__ __half g_WhhR[2 * GG * HH];
__device__ __half g_ht  [2 * BQ * HH];      // m-major h state, double buffered
__device__ unsigned g_count;
__device__ unsigned g_gen;

// ---------------- helpers ----------------
__device__ __forceinline__ void mmah(float* d, const unsigned* a, const unsigned* b) {
    asm volatile("mma.sync.aligned.m16n8k16.row.col.f32.f16.f16.f32 "
                 "{%0,%1,%2,%3}, {%4,%5,%6,%7}, {%8,%9}, {%0,%1,%2,%3};"
                 : "+f"(d[0]), "+f"(d[1]), "+f"(d[2]), "+f"(d[3])
                 : "r"(a[0]), "r"(a[1]), "r"(a[2]), "r"(a[3]), "r"(b[0]), "r"(b[1]));
}

__device__ __forceinline__ void ldsm4(unsigned& r0, unsigned& r1, unsigned& r2, unsigned& r3,
                                      unsigned addr) {
    asm volatile("ldmatrix.sync.aligned.m8n8.x4.shared.b16 {%0,%1,%2,%3}, [%4];"
                 : "=r"(r0), "=r"(r1), "=r"(r2), "=r"(r3) : "r"(addr));
}

__device__ __forceinline__ void cpasync16(void* smem_dst, const void* gsrc) {
    unsigned s = (unsigned)__cvta_generic_to_shared(smem_dst);
    asm volatile("cp.async.cg.shared.global [%0], [%1], 16;" :: "r"(s), "l"(gsrc));
}
__device__ __forceinline__ void cpcommit() { asm volatile("cp.async.commit_group;" ::: "memory"); }
template<int N> __device__ __forceinline__ void cpwaitN() {
    asm volatile("cp.async.wait_group %0;" :: "n"(N) : "memory");
}

__device__ __forceinline__ float sigm(float x)     { return 1.f / (1.f + __expf(-x)); }
__device__ __forceinline__ float tanhfast(float x) { return 2.f / (1.f + __expf(-2.f * x)) - 1.f; }

// ---------------- small utility kernels ----------------
__global__ void k_transpose_win(const float* __restrict__ Win, __half* __restrict__ WinT)
{
    int idx = blockIdx.x * blockDim.x + threadIdx.x;   // over HH*INP
    if (idx >= HH * INP) return;
    int n = idx / INP, k = idx % INP;
    WinT[idx] = (k < INLEN) ? __float2half_rn(Win[k * HH + n]) : __float2half_rn(0.f);
}

__global__ void k_round2(const float* __restrict__ A, __half* __restrict__ RA,
                         const float* __restrict__ B, __half* __restrict__ RB)
{
    int i = blockIdx.x * blockDim.x + threadIdx.x;
    if (i < 2 * GG * HH) { RA[i] = __float2half_rn(A[i]); RB[i] = __float2half_rn(B[i]); }
}

__global__ void k_reset()
{
    int i = blockIdx.x * blockDim.x + threadIdx.x;
    if (i < 2 * BQ * HH) g_ht[i] = __float2half_rn(0.f);
    if (i == 0) { g_count = 0; g_gen = 0; }
}

__global__ void k_build_feat(const float* __restrict__ x,
                             const float* __restrict__ mean,
                             const float* __restrict__ scale,
                             const float* __restrict__ emb,
                             __half* __restrict__ feat)
{
    int idx = blockIdx.x * blockDim.x + threadIdx.x;   // over MT*INP
    if (idx >= MT * INP) return;
    int c = idx % INP;
    int m = idx / INP;
    float v = 0.f;
    if (c < INLEN) {
        int blk = c / 11, r = c % 11;
        if (r < 8) {
            int k  = 4 * blk;
            int xi = (int)x[(size_t)m * NFEAT + k];
            v = emb[((size_t)blk * VV + xi) * EE + r];
        } else {
            int k = 4 * blk + (r - 7);
            v = (x[(size_t)m * NFEAT + k] - mean[k]) / scale[k];
        }
    }
    feat[idx] = __float2half_rn(v);
}

// ---------------- fp16 NT GEMM: 128x128 CTA, 8 warps of 32x64, BK=32(half), k16 mma ----
__device__ __forceinline__ void gemm_load_stage(__half* dstA, __half* dstW,
                                                const __half* A, const __half* W,
                                                int bm, int bn, int K, int k0, int tid)
{
#pragma unroll
    for (int i = 0; i < 2; i++) {
        int e   = tid + i * 256;      // 0..511
        int row = e >> 2;             // 0..127
        int q   = (e & 3) << 3;       // 0,8,16,24 halves
        cpasync16(dstA + row * 40 + q, A + (size_t)(bm + row) * K + k0 + q);
    }
#pragma unroll
    for (int i = 0; i < 2; i++) {
        int e   = tid + i * 256;
        int row = e >> 2;
        int q   = (e & 3) << 3;
        cpasync16(dstW + row * 40 + q, W + (size_t)(bn + row) * K + k0 + q);
    }
}

__global__ __launch_bounds__(256, 2)
void k_gemm_fp16(const __half* __restrict__ A, const __half* __restrict__ W,
                 const float* __restrict__ bias, void* __restrict__ Cv,
                 int M, int N, int K, int flags)   // bit0: relu, bit1: half output
{
    extern __shared__ __half smh[];
    __half* As = smh;                       // [3][128*40]
    __half* Ws = smh + 3 * ASTG_H;

    const int tid  = threadIdx.x;
    const int bm   = blockIdx.y * 128;
    const int bn   = blockIdx.x * 128;
    const int lane = tid & 31, warp = tid >> 5;
    const int wm   = (warp & 3) * 32;       // 4 m-warps, tile 32
    const int wn   = (warp >> 2) * 64;      // 2 n-warps, tile 64
    const int r    = lane >> 2, cq = lane & 3;
    const int NK   = K >> 5;                // K % 32 == 0

    const unsigned sbg = (unsigned)__cvta_generic_to_shared(smh);
    const int arow = lane & 15;
    const int kA   = (lane & 16) ? 8 : 0;   // halves
    const int brow = (lane & 7) + ((lane & 16) ? 8 : 0);
    const int kB   = (lane & 8) ? 8 : 0;    // halves
    const unsigned aoff = ((wm + arow) * 40 + kA) * 2;
    const unsigned boff = ((wn + brow) * 40 + kB) * 2;

    float acc[2][8][4];
#pragma unroll
    for (int mt = 0; mt < 2; mt++)
#pragma unroll
        for (int in = 0; in < 8; in++)
#pragma unroll
            for (int q = 0; q < 4; q++) acc[mt][in][q] = 0.f;

    gemm_load_stage(As, Ws, A, W, bm, bn, K, 0, tid); cpcommit();
    if (NK > 1) gemm_load_stage(As + ASTG_H, Ws + ASTG_H, A, W, bm, bn, K, 32, tid);
    cpcommit();

    for (int kc = 0; kc < NK; kc++) {
        if (kc + 1 < NK) cpwaitN<1>(); else cpwaitN<0>();
        __syncthreads();
        if (kc + 2 < NK) {
            int s = (kc + 2) % 3;
            gemm_load_stage(As + s * ASTG_H, Ws + s * ASTG_H, A, W, bm, bn, K,
                            (kc + 2) << 5, tid);
            cpcommit();
        }
        const unsigned asb = sbg + (kc % 3) * ASTG_B;
        const unsigned wsb = sbg + 3 * ASTG_B + (kc % 3) * ASTG_B;
#pragma unroll
        for (int kk = 0; kk < 32; kk += 16) {
            unsigned a[2][4], b[8][2];
#pragma unroll
            for (int mt = 0; mt < 2; mt++)
                ldsm4(a[mt][0], a[mt][1], a[mt][2], a[mt][3],
                      asb + aoff + (mt * 16 * 40 + kk) * 2);
#pragma unroll
            for (int p = 0; p < 4; p++) {
                unsigned t0, t1, t2, t3;
                ldsm4(t0, t1, t2, t3, wsb + boff + (p * 16 * 40 + kk) * 2);
                b[2 * p][0] = t0; b[2 * p][1] = t1;
                b[2 * p + 1][0] = t2; b[2 * p + 1][1] = t3;
            }
#pragma unroll
            for (int mt = 0; mt < 2; mt++)
#pragma unroll
                for (int in = 0; in < 8; in++)
                    mmah(acc[mt][in], a[mt], b[in]);
        }
    }

    const int doRelu = flags & 1;
    const int doHalf = flags & 2;
#pragma unroll
    for (int mt = 0; mt < 2; mt++) {
        int row = bm + wm + mt * 16 + r;
#pragma unroll
        for (int in = 0; in < 8; in++) {
            int col = bn + wn + in * 8 + 2 * cq;
            float2 bv = *(const float2*)(bias + col);
            float v0 = acc[mt][in][0] + bv.x;
            float v1 = acc[mt][in][1] + bv.y;
            float v2 = acc[mt][in][2] + bv.x;
            float v3 = acc[mt][in][3] + bv.y;
            if (doRelu) {
                v0 = fmaxf(v0, 0.f); v1 = fmaxf(v1, 0.f);
                v2 = fmaxf(v2, 0.f); v3 = fmaxf(v3, 0.f);
            }
            if (doHalf) {
                __half* C = (__half*)Cv;
                *(__half2*)(C + (size_t)row * N + col) =
                    __floats2half2_rn(v0, v1);
                *(__half2*)(C + (size_t)(row + 8) * N + col) =
                    __floats2half2_rn(v2, v3);
            } else {
                float* C = (float*)Cv;
                *(float2*)(C + (size_t)row * N + col)       = make_float2(v0, v1);
                *(float2*)(C + (size_t)(row + 8) * N + col) = make_float2(v2, v3);
            }
        }
    }
}

// ---------------- persistent recurrent LSTM layer (fp16 operands) ----------------
#define KCH 64
#define NCH 8
#define NCTA_PERSIST 128

__device__ __forceinline__ void load_ha(__half* dst, const __half* ht_in,
                                        int k0, int m0, int tid)
{
#pragma unroll
    for (int i = 0; i < 2; i++) {
        int s   = tid + i * 256;      // 0..511
        int row = s >> 3;             // m: 0..63
        int c8  = (s & 7) << 3;       // k: 0..56 halves
        cpasync16(dst + row * 72 + c8, ht_in + (size_t)(m0 + row) * HH + k0 + c8);
    }
}

__device__ __forceinline__ void load_xs(float* dst, const float* xw,
                                        int t, int m0, int j0, int tid)
{
#pragma unroll
    for (int i = 0; i < 4; i++) {
        int s   = tid + i * 256;
        int row = s >> 4;             // 0..63
        int q   = (s >> 2) & 3;
        int f4  = (s & 3) << 2;
        cpasync16(dst + row * 68 + q * 16 + f4,
                  xw + ((size_t)(m0 + row) * TT + t) * GG + q * HH + j0 + f4);
    }
}

__global__ __launch_bounds__(256, 1)
void k_lstm_persist(const float* __restrict__ xw, const __half* __restrict__ WhhR,
                    const float* __restrict__ bhh, __half* __restrict__ seq_out)
{
    extern __shared__ char smc[];
    __half* Bs = (__half*)smc;                    // [64][520] Whh slice
    __half* Ha = (__half*)(smc + P_HA_OFF);       // [3][64][72] h chunks
    float*  Xs = (float*)(smc + P_XS_OFF);        // [2][64][68] xw tiles
    float*  Gs = (float*)(smc + P_GS_OFF);        // [2][64][68] split-K partials

    const int tid   = threadIdx.x, lane = tid & 31, warp = tid >> 5;
    const int j0    = blockIdx.x * 16;
    const int m0    = blockIdx.y * 64;
    const int khalf = warp >> 2;
    const int wmw   = (warp & 1) * 32;
    const int wnw   = ((warp >> 1) & 1) * 32;
    const int jjt   = tid & 15;
    const int mgt   = tid >> 4;

    const unsigned sbB  = (unsigned)__cvta_generic_to_shared(Bs);
    const unsigned sbHa = (unsigned)__cvta_generic_to_shared(Ha);
    const int arow = lane & 15;
    const int kA   = (lane & 16) ? 8 : 0;
    const int brow = (lane & 7) + ((lane & 16) ? 8 : 0);
    const int kB   = (lane & 8) ? 8 : 0;
    const unsigned aoff = ((wmw + arow) * 72 + kA) * 2;
    const unsigned boff = ((wnw + brow) * 520 + kB) * 2;

    // one-time Bs load: row n = jj*4+q <- WhhR row q*512+j0+jj, full K (512 halves)
    {
#pragma unroll
        for (int i = 0; i < 16; i++) {
            int s  = tid + i * 256;       // 0..4095
            int n  = s >> 6;              // 0..63
            int c8 = (s & 63) << 3;       // 0..504
            int jj = n >> 2, q = n & 3;
            cpasync16(Bs + n * 520 + c8, WhhR + (size_t)(q * HH + j0 + jj) * HH + c8);
        }
        cpcommit();
    }
    float bh[4];
#pragma unroll
    for (int q = 0; q < 4; q++) bh[q] = bhh[q * HH + j0 + jjt];

    float cst[4] = {0.f, 0.f, 0.f, 0.f};

    load_xs(Xs, xw, 0, m0, j0, tid);  cpcommit();
    load_ha(Ha, g_ht, 0, m0, tid);    cpcommit();
    load_ha(Ha + 64 * 72, g_ht, KCH, m0, tid); cpcommit();

    for (int t = 0; t < TT; t++) {
        const int pin = t & 1;
        const __half* ht_in  = g_ht + (size_t)pin * (BQ * HH);
        __half*       ht_out = g_ht + (size_t)(pin ^ 1) * (BQ * HH);

        float acc[2][4][4];
#pragma unroll
        for (int mt = 0; mt < 2; mt++)
#pragma unroll
            for (int in = 0; in < 4; in++)
#pragma unroll
                for (int q = 0; q < 4; q++) acc[mt][in][q] = 0.f;

        for (int kc = 0; kc < NCH; kc++) {
            if (kc + 1 < NCH) cpwaitN<1>(); else cpwaitN<0>();
            __syncthreads();
            if (kc + 2 < NCH) {
                load_ha(Ha + ((kc + 2) % 3) * (64 * 72), ht_in, (kc + 2) * KCH, m0, tid);
                cpcommit();
            }
            if ((kc >> 2) == khalf) {
                const unsigned hb = sbHa + ((kc % 3) * 64 * 72) * 2;
                const int kg0 = kc * KCH;
#pragma unroll
                for (int kk = 0; kk < KCH; kk += 16) {
                    unsigned a[2][4];
#pragma unroll
                    for (int mt = 0; mt < 2; mt++)
                        ldsm4(a[mt][0], a[mt][1], a[mt][2], a[mt][3],
                              hb + aoff + (mt * 16 * 72 + kk) * 2);
                    unsigned b[4][2];
#pragma unroll
                    for (int p = 0; p < 2; p++) {
                        unsigned t0, t1, t2, t3;
                        ldsm4(t0, t1, t2, t3,
                              sbB + boff + (p * 16 * 520 + kg0 + kk) * 2);
                        b[2 * p][0] = t0; b[2 * p][1] = t1;
                        b[2 * p + 1][0] = t2; b[2 * p + 1][1] = t3;
                    }
#pragma unroll
                    for (int mt = 0; mt < 2; mt++)
#pragma unroll
                        for (int in = 0; in < 4; in++)
                            mmah(acc[mt][in], a[mt], b[in]);
                }
            }
        }

        // write split-K partials (disjoint per khalf; no pre-sync needed)
        {
            const int r = lane >> 2, cq = lane & 3;
            float* G = Gs + khalf * (64 * 68);
#pragma unroll
            for (int mt = 0; mt < 2; mt++) {
                int row = wmw + mt * 16 + r;
#pragma unroll
                for (int in = 0; in < 4; in++) {
                    int col = wnw + in * 8 + 2 * cq;
                    *(float2*)&G[row * 68 + col]       = make_float2(acc[mt][in][0], acc[mt][in][1]);
                    *(float2*)&G[(row + 8) * 68 + col] = make_float2(acc[mt][in][2], acc[mt][in][3]);
                }
            }
        }
        __syncthreads();

        // prefetch next step's xw tile
        if (t + 1 < TT) { load_xs(Xs + ((t + 1) & 1) * (64 * 68), xw, t + 1, m0, j0, tid); cpcommit(); }

        // epilogue: thread (jjt, m = mgt+16*it)
        const float* xs  = Xs + (t & 1) * (64 * 68);
        const float* GsA = Gs;
        const float* GsB = Gs + 64 * 68;
#pragma unroll
        for (int it = 0; it < 4; it++) {
            int m = mgt + it * 16;
            float4 ga = *(const float4*)&GsA[m * 68 + jjt * 4];
            float4 gb = *(const float4*)&GsB[m * 68 + jjt * 4];
            float gi = ga.x + gb.x + xs[m * 68 +      jjt] + bh[0];
            float gf = ga.y + gb.y + xs[m * 68 + 16 + jjt] + bh[1];
            float gg = ga.z + gb.z + xs[m * 68 + 32 + jjt] + bh[2];
            float go = ga.w + gb.w + xs[m * 68 + 48 + jjt] + bh[3];
            float iv = sigm(gi), fv = sigm(gf);
            float gv = tanhfast(gg), ov = sigm(go);
            float cv = fv * cst[it] + iv * gv;
            cst[it] = cv;
            float hv = ov * tanhfast(cv);
            ht_out[(size_t)(m0 + m) * HH + j0 + jjt] = __float2half_rn(hv);
            seq_out[((size_t)(m0 + m) * TT + t) * HH + j0 + jjt] =
                __float2half_rn(fmaxf(hv, 0.f));
        }

        // grid barrier
        __threadfence();
        __syncthreads();
        if (tid == 0) {
            atomicAdd(&g_count, 1u);
            if (blockIdx.x == 0 && blockIdx.y == 0) {
                while (*(volatile unsigned*)&g_count < (unsigned)NCTA_PERSIST * (unsigned)(t + 1)) { }
                __threadfence();
                *(volatile unsigned*)&g_gen = (unsigned)(t + 1);
            } else {
                while (*(volatile unsigned*)&g_gen < (unsigned)(t + 1)) { }
                __threadfence();
            }
        }
        __syncthreads();

        // prologue h chunks 0,1 for t+1
        if (t + 1 < TT) {
            const __half* hin2 = g_ht + (size_t)((t + 1) & 1) * (BQ * HH);
            load_ha(Ha, hin2, 0, m0, tid);             cpcommit();
            load_ha(Ha + 64 * 72, hin2, KCH, m0, tid); cpcommit();
        }
    }
}

// ---------------- heads ----------------
__global__ void k_head(const __half* __restrict__ seq,
                       const float* __restrict__ W_out, const float* __restrict__ b_out,
                       const float* __restrict__ W_cls, const float* __restrict__ b_cls,
                       float* __restrict__ out)
{
    int idx = blockIdx.x * blockDim.x + threadIdx.x;
    if (idx >= BQ * 560) return;
    int b = idx / 560, c = idx % 560;
    const __half* last = seq + ((size_t)b * TT + (TT - 1)) * HH;
    if (c < NCONT) {
        float s = b_out[c];
#pragma unroll 4
        for (int k = 0; k < HH; k++) s += __half2float(last[k]) * W_out[k * NCONT + c];
        out[b * NCONT + c] = s;
    } else {
        int cc = c - NCONT;
        int n = cc >> 5, v = cc & 31;
        float s = b_cls[n * VV + v];
        const float* w = W_cls + (size_t)n * HH * VV + v;
#pragma unroll 4
        for (int k = 0; k < HH; k++) s += __half2float(last[k]) * w[k * VV];
        out[BQ * NCONT + (size_t)b * (NCAT * VV) + cc] = s;
    }
}

// ---------------- launch ----------------
extern "C" void kernel_launch(void* const* d_in, const int* in_sizes, int n_in,
                              void* d_out, int out_size)
{
    const float* x      = (const float*)d_in[0];
    const float* smean  = (const float*)d_in[1];
    const float* sscale = (const float*)d_in[2];
    const float* emb    = (const float*)d_in[3];
    const float* W_in   = (const float*)d_in[4];
    const float* b_in   = (const float*)d_in[5];
    const float* Wih    = (const float*)d_in[6];
    const float* Whh    = (const float*)d_in[7];
    const float* bih    = (const float*)d_in[8];
    const float* bhh    = (const float*)d_in[9];
    const float* W_out  = (const float*)d_in[10];
    const float* b_out  = (const float*)d_in[11];
    const float* W_cls  = (const float*)d_in[12];
    const float* b_cls  = (const float*)d_in[13];
    float* out = (float*)d_out;

    __half *feat, *seq0, *seq1, *winT, *wihR, *whhR;
    float *xw;
    cudaGetSymbolAddress((void**)&feat, g_feat);
    cudaGetSymbolAddress((void**)&seq0, g_seq0);
    cudaGetSymbolAddress((void**)&seq1, g_seq1);
    cudaGetSymbolAddress((void**)&xw,   g_xw);
    cudaGetSymbolAddress((void**)&winT, g_WinT);
    cudaGetSymbolAddress((void**)&wihR, g_WihR);
    cudaGetSymbolAddress((void**)&whhR, g_WhhR);

    cudaFuncSetAttribute(k_lstm_persist, cudaFuncAttributeMaxDynamicSharedMemorySize,
                         PERSIST_SMEM);
    cudaFuncSetAttribute(k_gemm_fp16, cudaFuncAttributeMaxDynamicSharedMemorySize,
                         GEMM_SMEM);

    k_transpose_win<<<(HH * INP + 255) / 256, 256>>>(W_in, winT);
    k_round2<<<(2 * GG * HH + 255) / 256, 256>>>(Wih, wihR, Whh, whhR);
    k_build_feat<<<(MT * INP + 255) / 256, 256>>>(x, smean, sscale, emb, feat);

    // input projection: seq0 = half(relu(feat @ W_in + b_in)), K=192
    {
        dim3 grid(HH / 128, MT / 128);
        k_gemm_fp16<<<grid, 256, GEMM_SMEM>>>(feat, winT, b_in, seq0, MT, HH, INP, 3);
    }

    const __half* seq_in  = seq0;
    __half*       seq_out = seq1;
    for (int l = 0; l < 2; l++) {
        const __half* Wih_l = wihR + (size_t)l * GG * HH;
        const __half* Whh_l = whhR + (size_t)l * GG * HH;
        const float*  bih_l = bih  + (size_t)l * GG;
        const float*  bhh_l = bhh  + (size_t)l * GG;

        // xw = seq_in @ Wih^T + bih  (fp32 output)
        {
            dim3 grid(GG / 128, MT / 128);
            k_gemm_fp16<<<grid, 256, GEMM_SMEM>>>(seq_in, Wih_l, bih_l, xw, MT, GG, HH, 0);
        }
        k_reset<<<(2 * BQ * HH + 255) / 256, 256>>>();
        {
            dim3 grid(HH / 16, BQ / 64);   // (32, 4) = 128 CTAs
            k_lstm_persist<<<grid, 256, PERSIST_SMEM>>>(xw, Whh_l, bhh_l, seq_out);
        }
        const __half* tmp_in = seq_out;
        seq_out = (__half*)seq_in;
        seq_in  = tmp_in;
    }

    k_head<<<(BQ * 560 + 255) / 256, 256>>>(seq_in, W_out, b_out, W_cls, b_cls, out);
}

// round 9
// speedup vs baseline: 6.5909x; 1.0184x over previous
#include <cuda_runtime.h>
#include <cuda_fp16.h>
#include <math.h>
#include <stdint.h>

// ---------------- problem constants ----------------
#define BQ     256
#define TT     100
#define NFEAT  64
#define VV     32
#define EE     8
#define HH     512
#define NCAT   16
#define NCONT  48
#define INLEN  176
#define INP    192        // padded K for input projection
#define GG     2048
#define MT     (BQ*TT)

// persist smem (bytes): Bs half[64][520] + Ha half[3][64][72] + Xs f32[2][64][68] + Gs f32[2][64][68]
#define P_BS_B   (64*520*2)                 // 66,560
#define P_HA_B   (3*64*72*2)                // 27,648
#define P_XS_B   (2*64*68*4)                // 34,816
#define P_GS_B   (2*64*68*4)                // 34,816
#define P_HA_OFF (P_BS_B)
#define P_XS_OFF (P_BS_B + P_HA_B)
#define P_GS_OFF (P_BS_B + P_HA_B + P_XS_B)
#define PERSIST_SMEM (P_BS_B + P_HA_B + P_XS_B + P_GS_B)   // 163,840 B

// GEMM smem: 4 stages x (A 128x40 + W 128x40) halves
#define ASTG_H   (128*40)
#define ASTG_B   (ASTG_H*2)                 // 10,240 B
#define GEMM_SMEM (4 * 2 * ASTG_B)          // 81,920 B

// ---------------- scratch ----------------
__device__ __half g_feat[MT * INP + 64];
__device__ __half g_seq0[MT * HH + 64];
__device__ __half g_seq1[MT * HH + 64];
__device__ float  g_xw  [(size_t)MT * GG];
__device__ __half g_WinT[HH * INP + 64];
__device__ __half g_WihR[2 * GG * HH];
__device__ __half g_WhhR[2 * GG * HH];
__device__ __half g_ht  [2 * BQ * HH];      // m-major h state, double buffered
__device__ unsigned g_cnt[4];               // per-m0-group barrier counters
__device__ unsigned g_gen[4];

// ---------------- helpers ----------------
__device__ __forceinline__ void mmah(float* d, const unsigned* a, const unsigned* b) {
    asm volatile("mma.sync.aligned.m16n8k16.row.col.f32.f16.f16.f32 "
                 "{%0,%1,%2,%3}, {%4,%5,%6,%7}, {%8,%9}, {%0,%1,%2,%3};"
                 : "+f"(d[0]), "+f"(d[1]), "+f"(d[2]), "+f"(d[3])
                 : "r"(a[0]), "r"(a[1]), "r"(a[2]), "r"(a[3]), "r"(b[0]), "r"(b[1]));
}

__device__ __forceinline__ void ldsm4(unsigned& r0, unsigned& r1, unsigned& r2, unsigned& r3,
                                      unsigned addr) {
    asm volatile("ldmatrix.sync.aligned.m8n8.x4.shared.b16 {%0,%1,%2,%3}, [%4];"
                 : "=r"(r0), "=r"(r1), "=r"(r2), "=r"(r3) : "r"(addr));
}

__device__ __forceinline__ void cpasync16(void* smem_dst, const void* gsrc) {
    unsigned s = (unsigned)__cvta_generic_to_shared(smem_dst);
    asm volatile("cp.async.cg.shared.global [%0], [%1], 16;" :: "r"(s), "l"(gsrc));
}
__device__ __forceinline__ void cpcommit() { asm volatile("cp.async.commit_group;" ::: "memory"); }
template<int N> __device__ __forceinline__ void cpwaitN() {
    asm volatile("cp.async.wait_group %0;" :: "n"(N) : "memory");
}

__device__ __forceinline__ float sigm(float x)     { return 1.f / (1.f + __expf(-x)); }
__device__ __forceinline__ float tanhfast(float x) { return 2.f / (1.f + __expf(-2.f * x)) - 1.f; }

// ---------------- small utility kernels ----------------
__global__ void k_transpose_win(const float* __restrict__ Win, __half* __restrict__ WinT)
{
    int idx = blockIdx.x * blockDim.x + threadIdx.x;   // over HH*INP
    if (idx >= HH * INP) return;
    int n = idx / INP, k = idx % INP;
    WinT[idx] = (k < INLEN) ? __float2half_rn(Win[k * HH + n]) : __float2half_rn(0.f);
}

__global__ void k_round2(const float* __restrict__ A, __half* __restrict__ RA,
                         const float* __restrict__ B, __half* __restrict__ RB)
{
    int i = blockIdx.x * blockDim.x + threadIdx.x;
    if (i < 2 * GG * HH) { RA[i] = __float2half_rn(A[i]); RB[i] = __float2half_rn(B[i]); }
}

__global__ void k_reset()
{
    int i = blockIdx.x * blockDim.x + threadIdx.x;
    if (i < 2 * BQ * HH) g_ht[i] = __float2half_rn(0.f);
    if (i < 4) { g_cnt[i] = 0; g_gen[i] = 0; }
}

__global__ void k_build_feat(const float* __restrict__ x,
                             const float* __restrict__ mean,
                             const float* __restrict__ scale,
                             const float* __restrict__ emb,
                             __half* __restrict__ feat)
{
    int idx = blockIdx.x * blockDim.x + threadIdx.x;   // over MT*INP
    if (idx >= MT * INP) return;
    int c = idx % INP;
    int m = idx / INP;
    float v = 0.f;
    if (c < INLEN) {
        int blk = c / 11, r = c % 11;
        if (r < 8) {
            int k  = 4 * blk;
            int xi = (int)x[(size_t)m * NFEAT + k];
            v = emb[((size_t)blk * VV + xi) * EE + r];
        } else {
            int k = 4 * blk + (r - 7);
            v = (x[(size_t)m * NFEAT + k] - mean[k]) / scale[k];
        }
    }
    feat[idx] = __float2half_rn(v);
}

// ---------------- fp16 NT GEMM: 128x128 CTA, 8 warps of 32x64, BK=32(half), 4-stage ----
__device__ __forceinline__ void gemm_load_stage(__half* dstA, __half* dstW,
                                                const __half* A, const __half* W,
                                                int bm, int bn, int K, int k0, int tid)
{
#pragma unroll
    for (int i = 0; i < 2; i++) {
        int e   = tid + i * 256;      // 0..511
        int row = e >> 2;             // 0..127
        int q   = (e & 3) << 3;       // 0,8,16,24 halves
        cpasync16(dstA + row * 40 + q, A + (size_t)(bm + row) * K + k0 + q);
    }
#pragma unroll
    for (int i = 0; i < 2; i++) {
        int e   = tid + i * 256;
        int row = e >> 2;
        int q   = (e & 3) << 3;
        cpasync16(dstW + row * 40 + q, W + (size_t)(bn + row) * K + k0 + q);
    }
}

__global__ __launch_bounds__(256, 2)
void k_gemm_fp16(const __half* __restrict__ A, const __half* __restrict__ W,
                 const float* __restrict__ bias, void* __restrict__ Cv,
                 int M, int N, int K, int flags)   // bit0: relu, bit1: half output
{
    extern __shared__ __half smh[];
    __half* As = smh;                       // [4][128*40]
    __half* Ws = smh + 4 * ASTG_H;

    const int tid  = threadIdx.x;
    const int bm   = blockIdx.y * 128;
    const int bn   = blockIdx.x * 128;
    const int lane = tid & 31, warp = tid >> 5;
    const int wm   = (warp & 3) * 32;       // 4 m-warps, tile 32
    const int wn   = (warp >> 2) * 64;      // 2 n-warps, tile 64
    const int r    = lane >> 2, cq = lane & 3;
    const int NK   = K >> 5;                // K % 32 == 0, NK >= 3

    const unsigned sbg = (unsigned)__cvta_generic_to_shared(smh);
    const int arow = lane & 15;
    const int kA   = (lane & 16) ? 8 : 0;   // halves
    const int brow = (lane & 7) + ((lane & 16) ? 8 : 0);
    const int kB   = (lane & 8) ? 8 : 0;    // halves
    const unsigned aoff = ((wm + arow) * 40 + kA) * 2;
    const unsigned boff = ((wn + brow) * 40 + kB) * 2;

    float acc[2][8][4];
#pragma unroll
    for (int mt = 0; mt < 2; mt++)
#pragma unroll
        for (int in = 0; in < 8; in++)
#pragma unroll
            for (int q = 0; q < 4; q++) acc[mt][in][q] = 0.f;

    gemm_load_stage(As, Ws, A, W, bm, bn, K, 0, tid); cpcommit();
    gemm_load_stage(As + ASTG_H, Ws + ASTG_H, A, W, bm, bn, K, 32, tid); cpcommit();
    gemm_load_stage(As + 2 * ASTG_H, Ws + 2 * ASTG_H, A, W, bm, bn, K, 64, tid); cpcommit();

    for (int kc = 0; kc < NK; kc++) {
        if      (kc < NK - 2) cpwaitN<2>();
        else if (kc < NK - 1) cpwaitN<1>();
        else                  cpwaitN<0>();
        __syncthreads();
        if (kc + 3 < NK) {
            int s = (kc + 3) & 3;
            gemm_load_stage(As + s * ASTG_H, Ws + s * ASTG_H, A, W, bm, bn, K,
                            (kc + 3) << 5, tid);
            cpcommit();
        }
        const unsigned asb = sbg + (kc & 3) * ASTG_B;
        const unsigned wsb = sbg + 4 * ASTG_B + (kc & 3) * ASTG_B;
#pragma unroll
        for (int kk = 0; kk < 32; kk += 16) {
            unsigned a[2][4], b[8][2];
#pragma unroll
            for (int mt = 0; mt < 2; mt++)
                ldsm4(a[mt][0], a[mt][1], a[mt][2], a[mt][3],
                      asb + aoff + (mt * 16 * 40 + kk) * 2);
#pragma unroll
            for (int p = 0; p < 4; p++) {
                unsigned t0, t1, t2, t3;
                ldsm4(t0, t1, t2, t3, wsb + boff + (p * 16 * 40 + kk) * 2);
                b[2 * p][0] = t0; b[2 * p][1] = t1;
                b[2 * p + 1][0] = t2; b[2 * p + 1][1] = t3;
            }
#pragma unroll
            for (int mt = 0; mt < 2; mt++)
#pragma unroll
                for (int in = 0; in < 8; in++)
                    mmah(acc[mt][in], a[mt], b[in]);
        }
    }

    const int doRelu = flags & 1;
    const int doHalf = flags & 2;
#pragma unroll
    for (int mt = 0; mt < 2; mt++) {
        int row = bm + wm + mt * 16 + r;
#pragma unroll
        for (int in = 0; in < 8; in++) {
            int col = bn + wn + in * 8 + 2 * cq;
            float2 bv = *(const float2*)(bias + col);
            float v0 = acc[mt][in][0] + bv.x;
            float v1 = acc[mt][in][1] + bv.y;
            float v2 = acc[mt][in][2] + bv.x;
            float v3 = acc[mt][in][3] + bv.y;
            if (doRelu) {
                v0 = fmaxf(v0, 0.f); v1 = fmaxf(v1, 0.f);
                v2 = fmaxf(v2, 0.f); v3 = fmaxf(v3, 0.f);
            }
            if (doHalf) {
                __half* C = (__half*)Cv;
                *(__half2*)(C + (size_t)row * N + col) =
                    __floats2half2_rn(v0, v1);
                *(__half2*)(C + (size_t)(row + 8) * N + col) =
                    __floats2half2_rn(v2, v3);
            } else {
                float* C = (float*)Cv;
                *(float2*)(C + (size_t)row * N + col)       = make_float2(v0, v1);
                *(float2*)(C + (size_t)(row + 8) * N + col) = make_float2(v2, v3);
            }
        }
    }
}

// ---------------- persistent recurrent LSTM layer (fp16 operands) ----------------
#define KCH 64
#define NCH 8

__device__ __forceinline__ void load_ha(__half* dst, const __half* ht_in,
                                        int k0, int m0, int tid)
{
#pragma unroll
    for (int i = 0; i < 2; i++) {
        int s   = tid + i * 256;      // 0..511
        int row = s >> 3;             // m: 0..63
        int c8  = (s & 7) << 3;       // k: 0..56 halves
        cpasync16(dst + row * 72 + c8, ht_in + (size_t)(m0 + row) * HH + k0 + c8);
    }
}

__device__ __forceinline__ void load_xs(float* dst, const float* xw,
                                        int t, int m0, int j0, int tid)
{
#pragma unroll
    for (int i = 0; i < 4; i++) {
        int s   = tid + i * 256;
        int row = s >> 4;             // 0..63
        int q   = (s >> 2) & 3;
        int f4  = (s & 3) << 2;
        cpasync16(dst + row * 68 + q * 16 + f4,
                  xw + ((size_t)(m0 + row) * TT + t) * GG + q * HH + j0 + f4);
    }
}

__global__ __launch_bounds__(256, 1)
void k_lstm_persist(const float* __restrict__ xw, const __half* __restrict__ WhhR,
                    const float* __restrict__ bhh, __half* __restrict__ seq_out)
{
    extern __shared__ char smc[];
    __half* Bs = (__half*)smc;                    // [64][520] Whh slice
    __half* Ha = (__half*)(smc + P_HA_OFF);       // [3][64][72] h chunks
    float*  Xs = (float*)(smc + P_XS_OFF);        // [2][64][68] xw tiles
    float*  Gs = (float*)(smc + P_GS_OFF);        // [2][64][68] split-K partials

    const int tid   = threadIdx.x, lane = tid & 31, warp = tid >> 5;
    const int j0    = blockIdx.x * 16;
    const int m0    = blockIdx.y * 64;
    const int grp   = blockIdx.y;                 // barrier group (32 CTAs)
    const int khalf = warp >> 2;
    const int wmw   = (warp & 1) * 32;
    const int wnw   = ((warp >> 1) & 1) * 32;
    const int jjt   = tid & 15;
    const int mgt   = tid >> 4;

    const unsigned sbB  = (unsigned)__cvta_generic_to_shared(Bs);
    const unsigned sbHa = (unsigned)__cvta_generic_to_shared(Ha);
    const int arow = lane & 15;
    const int kA   = (lane & 16) ? 8 : 0;
    const int brow = (lane & 7) + ((lane & 16) ? 8 : 0);
    const int kB   = (lane & 8) ? 8 : 0;
    const unsigned aoff = ((wmw + arow) * 72 + kA) * 2;
    const unsigned boff = ((wnw + brow) * 520 + kB) * 2;

    // one-time Bs load: row n = jj*4+q <- WhhR row q*512+j0+jj, full K (512 halves)
    {
#pragma unroll
        for (int i = 0; i < 16; i++) {
            int s  = tid + i * 256;       // 0..4095
            int n  = s >> 6;              // 0..63
            int c8 = (s & 63) << 3;       // 0..504
            int jj = n >> 2, q = n & 3;
            cpasync16(Bs + n * 520 + c8, WhhR + (size_t)(q * HH + j0 + jj) * HH + c8);
        }
        cpcommit();
    }
    float bh[4];
#pragma unroll
    for (int q = 0; q < 4; q++) bh[q] = bhh[q * HH + j0 + jjt];

    float cst[4] = {0.f, 0.f, 0.f, 0.f};

    load_xs(Xs, xw, 0, m0, j0, tid);  cpcommit();
    load_ha(Ha, g_ht, 0, m0, tid);    cpcommit();
    load_ha(Ha + 64 * 72, g_ht, KCH, m0, tid); cpcommit();

    for (int t = 0; t < TT; t++) {
        const int pin = t & 1;
        const __half* ht_in  = g_ht + (size_t)pin * (BQ * HH);
        __half*       ht_out = g_ht + (size_t)(pin ^ 1) * (BQ * HH);

        float acc[2][4][4];
#pragma unroll
        for (int mt = 0; mt < 2; mt++)
#pragma unroll
            for (int in = 0; in < 4; in++)
#pragma unroll
                for (int q = 0; q < 4; q++) acc[mt][in][q] = 0.f;

        for (int kc = 0; kc < NCH; kc++) {
            if (kc + 1 < NCH) cpwaitN<1>(); else cpwaitN<0>();
            __syncthreads();
            if (kc + 2 < NCH) {
                load_ha(Ha + ((kc + 2) % 3) * (64 * 72), ht_in, (kc + 2) * KCH, m0, tid);
                cpcommit();
            }
            if ((kc >> 2) == khalf) {
                const unsigned hb = sbHa + ((kc % 3) * 64 * 72) * 2;
                const int kg0 = kc * KCH;
#pragma unroll
                for (int kk = 0; kk < KCH; kk += 16) {
                    unsigned a[2][4];
#pragma unroll
                    for (int mt = 0; mt < 2; mt++)
                        ldsm4(a[mt][0], a[mt][1], a[mt][2], a[mt][3],
                              hb + aoff + (mt * 16 * 72 + kk) * 2);
                    unsigned b[4][2];
#pragma unroll
                    for (int p = 0; p < 2; p++) {
                        unsigned t0, t1, t2, t3;
                        ldsm4(t0, t1, t2, t3,
                              sbB + boff + (p * 16 * 520 + kg0 + kk) * 2);
                        b[2 * p][0] = t0; b[2 * p][1] = t1;
                        b[2 * p + 1][0] = t2; b[2 * p + 1][1] = t3;
                    }
#pragma unroll
                    for (int mt = 0; mt < 2; mt++)
#pragma unroll
                        for (int in = 0; in < 4; in++)
                            mmah(acc[mt][in], a[mt], b[in]);
                }
            }
        }

        // write split-K partials (disjoint per khalf)
        {
            const int r = lane >> 2, cq = lane & 3;
            float* G = Gs + khalf * (64 * 68);
#pragma unroll
            for (int mt = 0; mt < 2; mt++) {
                int row = wmw + mt * 16 + r;
#pragma unroll
                for (int in = 0; in < 4; in++) {
                    int col = wnw + in * 8 + 2 * cq;
                    *(float2*)&G[row * 68 + col]       = make_float2(acc[mt][in][0], acc[mt][in][1]);
                    *(float2*)&G[(row + 8) * 68 + col] = make_float2(acc[mt][in][2], acc[mt][in][3]);
                }
            }
        }
        __syncthreads();

        // prefetch next step's xw tile
        if (t + 1 < TT) { load_xs(Xs + ((t + 1) & 1) * (64 * 68), xw, t + 1, m0, j0, tid); cpcommit(); }

        // epilogue: thread (jjt, m = mgt+16*it)
        const float* xs  = Xs + (t & 1) * (64 * 68);
        const float* GsA = Gs;
        const float* GsB = Gs + 64 * 68;
#pragma unroll
        for (int it = 0; it < 4; it++) {
            int m = mgt + it * 16;
            float4 ga = *(const float4*)&GsA[m * 68 + jjt * 4];
            float4 gb = *(const float4*)&GsB[m * 68 + jjt * 4];
            float gi = ga.x + gb.x + xs[m * 68 +      jjt] + bh[0];
            float gf = ga.y + gb.y + xs[m * 68 + 16 + jjt] + bh[1];
            float gg = ga.z + gb.z + xs[m * 68 + 32 + jjt] + bh[2];
            float go = ga.w + gb.w + xs[m * 68 + 48 + jjt] + bh[3];
            float iv = sigm(gi), fv = sigm(gf);
            float gv = tanhfast(gg), ov = sigm(go);
            float cv = fv * cst[it] + iv * gv;
            cst[it] = cv;
            float hv = ov * tanhfast(cv);
            ht_out[(size_t)(m0 + m) * HH + j0 + jjt] = __float2half_rn(hv);
            seq_out[((size_t)(m0 + m) * TT + t) * HH + j0 + jjt] =
                __float2half_rn(fmaxf(hv, 0.f));
        }

        // per-m0-group barrier (32 CTAs), last-arriver release, cumulative counts
        __threadfence();
        __syncthreads();
        if (tid == 0) {
            unsigned old = atomicAdd(&g_cnt[grp], 1u);
            if (old == 32u * (unsigned)(t + 1) - 1u) {
                __threadfence();
                *(volatile unsigned*)&g_gen[grp] = (unsigned)(t + 1);
            } else {
                while (*(volatile unsigned*)&g_gen[grp] < (unsigned)(t + 1)) { }
                __threadfence();
            }
        }
        __syncthreads();

        // prologue h chunks 0,1 for t+1
        if (t + 1 < TT) {
            const __half* hin2 = g_ht + (size_t)((t + 1) & 1) * (BQ * HH);
            load_ha(Ha, hin2, 0, m0, tid);             cpcommit();
            load_ha(Ha + 64 * 72, hin2, KCH, m0, tid); cpcommit();
        }
    }
}

// ---------------- heads ----------------
__global__ void k_head(const __half* __restrict__ seq,
                       const float* __restrict__ W_out, const float* __restrict__ b_out,
                       const float* __restrict__ W_cls, const float* __restrict__ b_cls,
                       float* __restrict__ out)
{
    int idx = blockIdx.x * blockDim.x + threadIdx.x;
    if (idx >= BQ * 560) return;
    int b = idx / 560, c = idx % 560;
    const __half* last = seq + ((size_t)b * TT + (TT - 1)) * HH;
    if (c < NCONT) {
        float s = b_out[c];
#pragma unroll 4
        for (int k = 0; k < HH; k++) s += __half2float(last[k]) * W_out[k * NCONT + c];
        out[b * NCONT + c] = s;
    } else {
        int cc = c - NCONT;
        int n = cc >> 5, v = cc & 31;
        float s = b_cls[n * VV + v];
        const float* w = W_cls + (size_t)n * HH * VV + v;
#pragma unroll 4
        for (int k = 0; k < HH; k++) s += __half2float(last[k]) * w[k * VV];
        out[BQ * NCONT + (size_t)b * (NCAT * VV) + cc] = s;
    }
}

// ---------------- launch ----------------
extern "C" void kernel_launch(void* const* d_in, const int* in_sizes, int n_in,
                              void* d_out, int out_size)
{
    const float* x      = (const float*)d_in[0];
    const float* smean  = (const float*)d_in[1];
    const float* sscale = (const float*)d_in[2];
    const float* emb    = (const float*)d_in[3];
    const float* W_in   = (const float*)d_in[4];
    const float* b_in   = (const float*)d_in[5];
    const float* Wih    = (const float*)d_in[6];
    const float* Whh    = (const float*)d_in[7];
    const float* bih    = (const float*)d_in[8];
    const float* bhh    = (const float*)d_in[9];
    const float* W_out  = (const float*)d_in[10];
    const float* b_out  = (const float*)d_in[11];
    const float* W_cls  = (const float*)d_in[12];
    const float* b_cls  = (const float*)d_in[13];
    float* out = (float*)d_out;

    __half *feat, *seq0, *seq1, *winT, *wihR, *whhR;
    float *xw;
    cudaGetSymbolAddress((void**)&feat, g_feat);
    cudaGetSymbolAddress((void**)&seq0, g_seq0);
    cudaGetSymbolAddress((void**)&seq1, g_seq1);
    cudaGetSymbolAddress((void**)&xw,   g_xw);
    cudaGetSymbolAddress((void**)&winT, g_WinT);
    cudaGetSymbolAddress((void**)&wihR, g_WihR);
    cudaGetSymbolAddress((void**)&whhR, g_WhhR);

    cudaFuncSetAttribute(k_lstm_persist, cudaFuncAttributeMaxDynamicSharedMemorySize,
                         PERSIST_SMEM);
    cudaFuncSetAttribute(k_gemm_fp16, cudaFuncAttributeMaxDynamicSharedMemorySize,
                         GEMM_SMEM);

    k_transpose_win<<<(HH * INP + 255) / 256, 256>>>(W_in, winT);
    k_round2<<<(2 * GG * HH + 255) / 256, 256>>>(Wih, wihR, Whh, whhR);
    k_build_feat<<<(MT * INP + 255) / 256, 256>>>(x, smean, sscale, emb, feat);

    // input projection: seq0 = half(relu(feat @ W_in + b_in)), K=192
    {
        dim3 grid(HH / 128, MT / 128);
        k_gemm_fp16<<<grid, 256, GEMM_SMEM>>>(feat, winT, b_in, seq0, MT, HH, INP, 3);
    }

    const __half* seq_in  = seq0;
    __half*       seq_out = seq1;
    for (int l = 0; l < 2; l++) {
        const __half* Wih_l = wihR + (size_t)l * GG * HH;
        const __half* Whh_l = whhR + (size_t)l * GG * HH;
        const float*  bih_l = bih  + (size_t)l * GG;
        const float*  bhh_l = bhh  + (size_t)l * GG;

        // xw = seq_in @ Wih^T + bih  (fp32 output)
        {
            dim3 grid(GG / 128, MT / 128);
            k_gemm_fp16<<<grid, 256, GEMM_SMEM>>>(seq_in, Wih_l, bih_l, xw, MT, GG, HH, 0);
        }
        k_reset<<<(2 * BQ * HH + 255) / 256, 256>>>();
        {
            dim3 grid(HH / 16, BQ / 64);   // (32, 4) = 128 CTAs
            k_lstm_persist<<<grid, 256, PERSIST_SMEM>>>(xw, Whh_l, bhh_l, seq_out);
        }
        const __half* tmp_in = seq_out;
        seq_out = (__half*)seq_in;
        seq_in  = tmp_in;
    }

    k_head<<<(BQ * 560 + 255) / 256, 256>>>(seq_in, W_out, b_out, W_cls, b_cls, out);
}

// round 10
// speedup vs baseline: 7.1350x; 1.0825x over previous
#include <cuda_runtime.h>
#include <cuda_fp16.h>
#include <math.h>
#include <stdint.h>

// ---------------- problem constants ----------------
#define BQ     256
#define TT     100
#define NFEAT  64
#define VV     32
#define EE     8
#define HH     512
#define NCAT   16
#define NCONT  48
#define INLEN  176
#define INP    192        // padded K for input projection
#define GG     2048
#define MT     (BQ*TT)

// persist smem (bytes): Bs half[64][520] + Ha half[8][64][72] + Xs f32[2][64][68] + Gs f32[2][64][68]
#define P_BS_B   (64*520*2)                 // 66,560
#define P_HA_B   (8*64*72*2)                // 73,728
#define P_XS_B   (2*64*68*4)                // 34,816
#define P_GS_B   (2*64*68*4)                // 34,816
#define P_HA_OFF (P_BS_B)
#define P_XS_OFF (P_BS_B + P_HA_B)
#define P_GS_OFF (P_BS_B + P_HA_B + P_XS_B)
#define PERSIST_SMEM (P_BS_B + P_HA_B + P_XS_B + P_GS_B)   // 209,920 B

// GEMM smem: 4 stages x (A 128x40 + W 128x40) halves
#define ASTG_H   (128*40)
#define ASTG_B   (ASTG_H*2)                 // 10,240 B
#define GEMM_SMEM (4 * 2 * ASTG_B)          // 81,920 B

// ---------------- scratch ----------------
__device__ __half g_feat[MT * INP + 64];
__device__ __half g_seq0[MT * HH + 64];
__device__ __half g_seq1[MT * HH + 64];
__device__ float  g_xw  [(size_t)MT * GG];
__device__ __half g_WinT[HH * INP + 64];
__device__ __half g_WihR[2 * GG * HH];
__device__ __half g_WhhR[2 * GG * HH];
__device__ __half g_ht  [2 * BQ * HH];      // m-major h state, double buffered
__device__ unsigned g_cnt[4];               // per-m0-group barrier counters
__device__ unsigned g_gen[4];

// ---------------- helpers ----------------
__device__ __forceinline__ void mmah(float* d, const unsigned* a, const unsigned* b) {
    asm volatile("mma.sync.aligned.m16n8k16.row.col.f32.f16.f16.f32 "
                 "{%0,%1,%2,%3}, {%4,%5,%6,%7}, {%8,%9}, {%0,%1,%2,%3};"
                 : "+f"(d[0]), "+f"(d[1]), "+f"(d[2]), "+f"(d[3])
                 : "r"(a[0]), "r"(a[1]), "r"(a[2]), "r"(a[3]), "r"(b[0]), "r"(b[1]));
}

__device__ __forceinline__ void ldsm4(unsigned& r0, unsigned& r1, unsigned& r2, unsigned& r3,
                                      unsigned addr) {
    asm volatile("ldmatrix.sync.aligned.m8n8.x4.shared.b16 {%0,%1,%2,%3}, [%4];"
                 : "=r"(r0), "=r"(r1), "=r"(r2), "=r"(r3) : "r"(addr));
}

__device__ __forceinline__ void cpasync16(void* smem_dst, const void* gsrc) {
    unsigned s = (unsigned)__cvta_generic_to_shared(smem_dst);
    asm volatile("cp.async.cg.shared.global [%0], [%1], 16;" :: "r"(s), "l"(gsrc));
}
__device__ __forceinline__ void cpcommit() { asm volatile("cp.async.commit_group;" ::: "memory"); }
template<int N> __device__ __forceinline__ void cpwaitN() {
    asm volatile("cp.async.wait_group %0;" :: "n"(N) : "memory");
}

__device__ __forceinline__ float sigm(float x)     { return 1.f / (1.f + __expf(-x)); }
__device__ __forceinline__ float tanhfast(float x) { return 2.f / (1.f + __expf(-2.f * x)) - 1.f; }

__device__ __forceinline__ void bar_grp(int khalf) {
    if (khalf == 0) asm volatile("bar.sync 1, 128;" ::: "memory");
    else            asm volatile("bar.sync 2, 128;" ::: "memory");
}

// ---------------- small utility kernels ----------------
__global__ void k_transpose_win(const float* __restrict__ Win, __half* __restrict__ WinT)
{
    int idx = blockIdx.x * blockDim.x + threadIdx.x;   // over HH*INP
    if (idx >= HH * INP) return;
    int n = idx / INP, k = idx % INP;
    WinT[idx] = (k < INLEN) ? __float2half_rn(Win[k * HH + n]) : __float2half_rn(0.f);
}

__global__ void k_round2(const float* __restrict__ A, __half* __restrict__ RA,
                         const float* __restrict__ B, __half* __restrict__ RB)
{
    int i = blockIdx.x * blockDim.x + threadIdx.x;
    if (i < 2 * GG * HH) { RA[i] = __float2half_rn(A[i]); RB[i] = __float2half_rn(B[i]); }
}

__global__ void k_reset()
{
    int i = blockIdx.x * blockDim.x + threadIdx.x;
    if (i < 2 * BQ * HH) g_ht[i] = __float2half_rn(0.f);
    if (i < 4) { g_cnt[i] = 0; g_gen[i] = 0; }
}

__global__ void k_build_feat(const float* __restrict__ x,
                             const float* __restrict__ mean,
                             const float* __restrict__ scale,
                             const float* __restrict__ emb,
                             __half* __restrict__ feat)
{
    int idx = blockIdx.x * blockDim.x + threadIdx.x;   // over MT*INP
    if (idx >= MT * INP) return;
    int c = idx % INP;
    int m = idx / INP;
    float v = 0.f;
    if (c < INLEN) {
        int blk = c / 11, r = c % 11;
        if (r < 8) {
            int k  = 4 * blk;
            int xi = (int)x[(size_t)m * NFEAT + k];
            v = emb[((size_t)blk * VV + xi) * EE + r];
        } else {
            int k = 4 * blk + (r - 7);
            v = (x[(size_t)m * NFEAT + k] - mean[k]) / scale[k];
        }
    }
    feat[idx] = __float2half_rn(v);
}

// ---------------- fp16 NT GEMM: 128x128 CTA, 8 warps of 32x64, BK=32(half), 4-stage ----
__device__ __forceinline__ void gemm_load_stage(__half* dstA, __half* dstW,
                                                const __half* A, const __half* W,
                                                int bm, int bn, int K, int k0, int tid)
{
#pragma unroll
    for (int i = 0; i < 2; i++) {
        int e   = tid + i * 256;      // 0..511
        int row = e >> 2;             // 0..127
        int q   = (e & 3) << 3;       // 0,8,16,24 halves
        cpasync16(dstA + row * 40 + q, A + (size_t)(bm + row) * K + k0 + q);
    }
#pragma unroll
    for (int i = 0; i < 2; i++) {
        int e   = tid + i * 256;
        int row = e >> 2;
        int q   = (e & 3) << 3;
        cpasync16(dstW + row * 40 + q, W + (size_t)(bn + row) * K + k0 + q);
    }
}

__global__ __launch_bounds__(256, 2)
void k_gemm_fp16(const __half* __restrict__ A, const __half* __restrict__ W,
                 const float* __restrict__ bias, void* __restrict__ Cv,
                 int M, int N, int K, int flags)   // bit0: relu, bit1: half output
{
    extern __shared__ __half smh[];
    __half* As = smh;                       // [4][128*40]
    __half* Ws = smh + 4 * ASTG_H;

    const int tid  = threadIdx.x;
    const int bm   = blockIdx.y * 128;
    const int bn   = blockIdx.x * 128;
    const int lane = tid & 31, warp = tid >> 5;
    const int wm   = (warp & 3) * 32;       // 4 m-warps, tile 32
    const int wn   = (warp >> 2) * 64;      // 2 n-warps, tile 64
    const int r    = lane >> 2, cq = lane & 3;
    const int NK   = K >> 5;                // K % 32 == 0, NK >= 3

    const unsigned sbg = (unsigned)__cvta_generic_to_shared(smh);
    const int arow = lane & 15;
    const int kA   = (lane & 16) ? 8 : 0;   // halves
    const int brow = (lane & 7) + ((lane & 16) ? 8 : 0);
    const int kB   = (lane & 8) ? 8 : 0;    // halves
    const unsigned aoff = ((wm + arow) * 40 + kA) * 2;
    const unsigned boff = ((wn + brow) * 40 + kB) * 2;

    float acc[2][8][4];
#pragma unroll
    for (int mt = 0; mt < 2; mt++)
#pragma unroll
        for (int in = 0; in < 8; in++)
#pragma unroll
            for (int q = 0; q < 4; q++) acc[mt][in][q] = 0.f;

    gemm_load_stage(As, Ws, A, W, bm, bn, K, 0, tid); cpcommit();
    gemm_load_stage(As + ASTG_H, Ws + ASTG_H, A, W, bm, bn, K, 32, tid); cpcommit();
    gemm_load_stage(As + 2 * ASTG_H, Ws + 2 * ASTG_H, A, W, bm, bn, K, 64, tid); cpcommit();

    for (int kc = 0; kc < NK; kc++) {
        if      (kc < NK - 2) cpwaitN<2>();
        else if (kc < NK - 1) cpwaitN<1>();
        else                  cpwaitN<0>();
        __syncthreads();
        if (kc + 3 < NK) {
            int s = (kc + 3) & 3;
            gemm_load_stage(As + s * ASTG_H, Ws + s * ASTG_H, A, W, bm, bn, K,
                            (kc + 3) << 5, tid);
            cpcommit();
        }
        const unsigned asb = sbg + (kc & 3) * ASTG_B;
        const unsigned wsb = sbg + 4 * ASTG_B + (kc & 3) * ASTG_B;
#pragma unroll
        for (int kk = 0; kk < 32; kk += 16) {
            unsigned a[2][4], b[8][2];
#pragma unroll
            for (int mt = 0; mt < 2; mt++)
                ldsm4(a[mt][0], a[mt][1], a[mt][2], a[mt][3],
                      asb + aoff + (mt * 16 * 40 + kk) * 2);
#pragma unroll
            for (int p = 0; p < 4; p++) {
                unsigned t0, t1, t2, t3;
                ldsm4(t0, t1, t2, t3, wsb + boff + (p * 16 * 40 + kk) * 2);
                b[2 * p][0] = t0; b[2 * p][1] = t1;
                b[2 * p + 1][0] = t2; b[2 * p + 1][1] = t3;
            }
#pragma unroll
            for (int mt = 0; mt < 2; mt++)
#pragma unroll
                for (int in = 0; in < 8; in++)
                    mmah(acc[mt][in], a[mt], b[in]);
        }
    }

    const int doRelu = flags & 1;
    const int doHalf = flags & 2;
#pragma unroll
    for (int mt = 0; mt < 2; mt++) {
        int row = bm + wm + mt * 16 + r;
#pragma unroll
        for (int in = 0; in < 8; in++) {
            int col = bn + wn + in * 8 + 2 * cq;
            float2 bv = *(const float2*)(bias + col);
            float v0 = acc[mt][in][0] + bv.x;
            float v1 = acc[mt][in][1] + bv.y;
            float v2 = acc[mt][in][2] + bv.x;
            float v3 = acc[mt][in][3] + bv.y;
            if (doRelu) {
                v0 = fmaxf(v0, 0.f); v1 = fmaxf(v1, 0.f);
                v2 = fmaxf(v2, 0.f); v3 = fmaxf(v3, 0.f);
            }
            if (doHalf) {
                __half* C = (__half*)Cv;
                *(__half2*)(C + (size_t)row * N + col) =
                    __floats2half2_rn(v0, v1);
                *(__half2*)(C + (size_t)(row + 8) * N + col) =
                    __floats2half2_rn(v2, v3);
            } else {
                float* C = (float*)Cv;
                *(float2*)(C + (size_t)row * N + col)       = make_float2(v0, v1);
                *(float2*)(C + (size_t)(row + 8) * N + col) = make_float2(v2, v3);
            }
        }
    }
}

// ---------------- persistent recurrent LSTM layer (fp16, bulk h fetch) ----------------
// Per step: each khalf warp-group (128 thr) fetches its 4 h-chunks (32 KB) as ONE
// cp.async group, waits once, computes all 4 chunks with no intervening syncs.
// Commit order per iter: ..., xw(t), H(t), xw(t+1), H(t+1) -> wait_group 0 at step
// start drains xw(t) and H(t) together.

__device__ __forceinline__ void load_h_group(__half* Ha, const __half* ht_in,
                                             int m0, int khalf, int gtid)
{
#pragma unroll
    for (int i = 0; i < 16; i++) {
        int s   = gtid + i * 128;        // 0..2047
        int cl  = s >> 9;                // local chunk 0..3
        int row = (s >> 3) & 63;
        int c8  = (s & 7) << 3;
        int chunk = khalf * 4 + cl;
        cpasync16(Ha + (size_t)chunk * (64 * 72) + row * 72 + c8,
                  ht_in + (size_t)(m0 + row) * HH + chunk * 64 + c8);
    }
}

__device__ __forceinline__ void load_xs(float* dst, const float* xw,
                                        int t, int m0, int j0, int tid)
{
#pragma unroll
    for (int i = 0; i < 4; i++) {
        int s   = tid + i * 256;
        int row = s >> 4;             // 0..63
        int q   = (s >> 2) & 3;
        int f4  = (s & 3) << 2;
        cpasync16(dst + row * 68 + q * 16 + f4,
                  xw + ((size_t)(m0 + row) * TT + t) * GG + q * HH + j0 + f4);
    }
}

__global__ __launch_bounds__(256, 1)
void k_lstm_persist(const float* __restrict__ xw, const __half* __restrict__ WhhR,
                    const float* __restrict__ bhh, __half* __restrict__ seq_out)
{
    extern __shared__ char smc[];
    __half* Bs = (__half*)smc;                    // [64][520] Whh slice
    __half* Ha = (__half*)(smc + P_HA_OFF);       // [8][64][72] h chunks (all resident)
    float*  Xs = (float*)(smc + P_XS_OFF);        // [2][64][68] xw tiles
    float*  Gs = (float*)(smc + P_GS_OFF);        // [2][64][68] split-K partials

    const int tid   = threadIdx.x, lane = tid & 31, warp = tid >> 5;
    const int j0    = blockIdx.x * 16;
    const int m0    = blockIdx.y * 64;
    const int grp   = blockIdx.y;                 // barrier group (32 CTAs)
    const int khalf = warp >> 2;
    const int gtid  = tid & 127;
    const int wmw   = (warp & 1) * 32;
    const int wnw   = ((warp >> 1) & 1) * 32;
    const int jjt   = tid & 15;
    const int mgt   = tid >> 4;

    const unsigned sbB  = (unsigned)__cvta_generic_to_shared(Bs);
    const unsigned sbHa = (unsigned)__cvta_generic_to_shared(Ha);
    const int arow = lane & 15;
    const int kA   = (lane & 16) ? 8 : 0;
    const int brow = (lane & 7) + ((lane & 16) ? 8 : 0);
    const int kB   = (lane & 8) ? 8 : 0;
    const unsigned aoff = ((wmw + arow) * 72 + kA) * 2;
    const unsigned boff = ((wnw + brow) * 520 + kB) * 2;

    // one-time Bs load: row n = jj*4+q <- WhhR row q*512+j0+jj, full K (512 halves)
    {
#pragma unroll
        for (int i = 0; i < 16; i++) {
            int s  = tid + i * 256;       // 0..4095
            int n  = s >> 6;              // 0..63
            int c8 = (s & 63) << 3;       // 0..504
            int jj = n >> 2, q = n & 3;
            cpasync16(Bs + n * 520 + c8, WhhR + (size_t)(q * HH + j0 + jj) * HH + c8);
        }
        cpcommit();
    }
    float bh[4];
#pragma unroll
    for (int q = 0; q < 4; q++) bh[q] = bhh[q * HH + j0 + jjt];

    float cst[4] = {0.f, 0.f, 0.f, 0.f};

    // prologue: xw(0), H(0); full drain + full sync (covers Bs visibility too)
    load_xs(Xs, xw, 0, m0, j0, tid);           cpcommit();
    load_h_group(Ha, g_ht, m0, khalf, gtid);   cpcommit();
    cpwaitN<0>();
    __syncthreads();

    for (int t = 0; t < TT; t++) {
        // drain xw(t) + H(t); group-local visibility for this khalf's chunks
        cpwaitN<0>();
        bar_grp(khalf);

        float acc[2][4][4];
#pragma unroll
        for (int mt = 0; mt < 2; mt++)
#pragma unroll
            for (int in = 0; in < 4; in++)
#pragma unroll
                for (int q = 0; q < 4; q++) acc[mt][in][q] = 0.f;

#pragma unroll
        for (int cl = 0; cl < 4; cl++) {
            const int chunk = khalf * 4 + cl;
            const unsigned hb = sbHa + (unsigned)(chunk * 64 * 72 * 2);
            const int kg0 = chunk * 64;
#pragma unroll
            for (int kk = 0; kk < 64; kk += 16) {
                unsigned a[2][4];
#pragma unroll
                for (int mt = 0; mt < 2; mt++)
                    ldsm4(a[mt][0], a[mt][1], a[mt][2], a[mt][3],
                          hb + aoff + (mt * 16 * 72 + kk) * 2);
                unsigned b[4][2];
#pragma unroll
                for (int p = 0; p < 2; p++) {
                    unsigned t0, t1, t2, t3;
                    ldsm4(t0, t1, t2, t3,
                          sbB + boff + (p * 16 * 520 + kg0 + kk) * 2);
                    b[2 * p][0] = t0; b[2 * p][1] = t1;
                    b[2 * p + 1][0] = t2; b[2 * p + 1][1] = t3;
                }
#pragma unroll
                for (int mt = 0; mt < 2; mt++)
#pragma unroll
                    for (int in = 0; in < 4; in++)
                        mmah(acc[mt][in], a[mt], b[in]);
            }
        }

        // commit next step's xw tile early (overlaps epilogue + barrier)
        if (t + 1 < TT) { load_xs(Xs + ((t + 1) & 1) * (64 * 68), xw, t + 1, m0, j0, tid); cpcommit(); }

        // write split-K partials (disjoint per khalf)
        {
            const int r = lane >> 2, cq = lane & 3;
            float* G = Gs + khalf * (64 * 68);
#pragma unroll
            for (int mt = 0; mt < 2; mt++) {
                int row = wmw + mt * 16 + r;
#pragma unroll
                for (int in = 0; in < 4; in++) {
                    int col = wnw + in * 8 + 2 * cq;
                    *(float2*)&G[row * 68 + col]       = make_float2(acc[mt][in][0], acc[mt][in][1]);
                    *(float2*)&G[(row + 8) * 68 + col] = make_float2(acc[mt][in][2], acc[mt][in][3]);
                }
            }
        }
        __syncthreads();

        // epilogue: thread (jjt, m = mgt+16*it)
        const int pin = t & 1;
        __half* ht_out = g_ht + (size_t)(pin ^ 1) * (BQ * HH);
        const float* xs  = Xs + (t & 1) * (64 * 68);
        const float* GsA = Gs;
        const float* GsB = Gs + 64 * 68;
#pragma unroll
        for (int it = 0; it < 4; it++) {
            int m = mgt + it * 16;
            float4 ga = *(const float4*)&GsA[m * 68 + jjt * 4];
            float4 gb = *(const float4*)&GsB[m * 68 + jjt * 4];
            float gi = ga.x + gb.x + xs[m * 68 +      jjt] + bh[0];
            float gf = ga.y + gb.y + xs[m * 68 + 16 + jjt] + bh[1];
            float gg = ga.z + gb.z + xs[m * 68 + 32 + jjt] + bh[2];
            float go = ga.w + gb.w + xs[m * 68 + 48 + jjt] + bh[3];
            float iv = sigm(gi), fv = sigm(gf);
            float gv = tanhfast(gg), ov = sigm(go);
            float cv = fv * cst[it] + iv * gv;
            cst[it] = cv;
            float hv = ov * tanhfast(cv);
            ht_out[(size_t)(m0 + m) * HH + j0 + jjt] = __float2half_rn(hv);
            seq_out[((size_t)(m0 + m) * TT + t) * HH + j0 + jjt] =
                __float2half_rn(fmaxf(hv, 0.f));
        }

        // per-m0-group barrier (32 CTAs), last-arriver release, cumulative counts
        __threadfence();
        __syncthreads();
        if (tid == 0) {
            unsigned old = atomicAdd(&g_cnt[grp], 1u);
            if (old == 32u * (unsigned)(t + 1) - 1u) {
                __threadfence();
                *(volatile unsigned*)&g_gen[grp] = (unsigned)(t + 1);
            } else {
                while (*(volatile unsigned*)&g_gen[grp] < (unsigned)(t + 1)) { }
                __threadfence();
            }
        }
        __syncthreads();

        // issue H(t+1) bulk fetch (one group per khalf)
        if (t + 1 < TT) {
            const __half* hin2 = g_ht + (size_t)((t + 1) & 1) * (BQ * HH);
            load_h_group(Ha, hin2, m0, khalf, gtid);
            cpcommit();
        }
    }
}

// ---------------- heads ----------------
__global__ void k_head(const __half* __restrict__ seq,
                       const float* __restrict__ W_out, const float* __restrict__ b_out,
                       const float* __restrict__ W_cls, const float* __restrict__ b_cls,
                       float* __restrict__ out)
{
    int idx = blockIdx.x * blockDim.x + threadIdx.x;
    if (idx >= BQ * 560) return;
    int b = idx / 560, c = idx % 560;
    const __half* last = seq + ((size_t)b * TT + (TT - 1)) * HH;
    if (c < NCONT) {
        float s = b_out[c];
#pragma unroll 4
        for (int k = 0; k < HH; k++) s += __half2float(last[k]) * W_out[k * NCONT + c];
        out[b * NCONT + c] = s;
    } else {
        int cc = c - NCONT;
        int n = cc >> 5, v = cc & 31;
        float s = b_cls[n * VV + v];
        const float* w = W_cls + (size_t)n * HH * VV + v;
#pragma unroll 4
        for (int k = 0; k < HH; k++) s += __half2float(last[k]) * w[k * VV];
        out[BQ * NCONT + (size_t)b * (NCAT * VV) + cc] = s;
    }
}

// ---------------- launch ----------------
extern "C" void kernel_launch(void* const* d_in, const int* in_sizes, int n_in,
                              void* d_out, int out_size)
{
    const float* x      = (const float*)d_in[0];
    const float* smean  = (const float*)d_in[1];
    const float* sscale = (const float*)d_in[2];
    const float* emb    = (const float*)d_in[3];
    const float* W_in   = (const float*)d_in[4];
    const float* b_in   = (const float*)d_in[5];
    const float* Wih    = (const float*)d_in[6];
    const float* Whh    = (const float*)d_in[7];
    const float* bih    = (const float*)d_in[8];
    const float* bhh    = (const float*)d_in[9];
    const float* W_out  = (const float*)d_in[10];
    const float* b_out  = (const float*)d_in[11];
    const float* W_cls  = (const float*)d_in[12];
    const float* b_cls  = (const float*)d_in[13];
    float* out = (float*)d_out;

    __half *feat, *seq0, *seq1, *winT, *wihR, *whhR;
    float *xw;
    cudaGetSymbolAddress((void**)&feat, g_feat);
    cudaGetSymbolAddress((void**)&seq0, g_seq0);
    cudaGetSymbolAddress((void**)&seq1, g_seq1);
    cudaGetSymbolAddress((void**)&xw,   g_xw);
    cudaGetSymbolAddress((void**)&winT, g_WinT);
    cudaGetSymbolAddress((void**)&wihR, g_WihR);
    cudaGetSymbolAddress((void**)&whhR, g_WhhR);

    cudaFuncSetAttribute(k_lstm_persist, cudaFuncAttributeMaxDynamicSharedMemorySize,
                         PERSIST_SMEM);
    cudaFuncSetAttribute(k_gemm_fp16, cudaFuncAttributeMaxDynamicSharedMemorySize,
                         GEMM_SMEM);

    k_transpose_win<<<(HH * INP + 255) / 256, 256>>>(W_in, winT);
    k_round2<<<(2 * GG * HH + 255) / 256, 256>>>(Wih, wihR, Whh, whhR);
    k_build_feat<<<(MT * INP + 255) / 256, 256>>>(x, smean, sscale, emb, feat);

    // input projection: seq0 = half(relu(feat @ W_in + b_in)), K=192
    {
        dim3 grid(HH / 128, MT / 128);
        k_gemm_fp16<<<grid, 256, GEMM_SMEM>>>(feat, winT, b_in, seq0, MT, HH, INP, 3);
    }

    const __half* seq_in  = seq0;
    __half*       seq_out = seq1;
    for (int l = 0; l < 2; l++) {
        const __half* Wih_l = wihR + (size_t)l * GG * HH;
        const __half* Whh_l = whhR + (size_t)l * GG * HH;
        const float*  bih_l = bih  + (size_t)l * GG;
        const float*  bhh_l = bhh  + (size_t)l * GG;

        // xw = seq_in @ Wih^T + bih  (fp32 output)
        {
            dim3 grid(GG / 128, MT / 128);
            k_gemm_fp16<<<grid, 256, GEMM_SMEM>>>(seq_in, Wih_l, bih_l, xw, MT, GG, HH, 0);
        }
        k_reset<<<(2 * BQ * HH + 255) / 256, 256>>>();
        {
            dim3 grid(HH / 16, BQ / 64);   // (32, 4) = 128 CTAs
            k_lstm_persist<<<grid, 256, PERSIST_SMEM>>>(xw, Whh_l, bhh_l, seq_out);
        }
        const __half* tmp_in = seq_out;
        seq_out = (__half*)seq_in;
        seq_in  = tmp_in;
    }

    k_head<<<(BQ * 560 + 255) / 256, 256>>>(seq_in, W_out, b_out, W_cls, b_cls, out);
}